// round 8
// baseline (speedup 1.0000x reference)
#include <cuda_runtime.h>
#include <cuda_bf16.h>
#include <cstdint>

// Problem constants (fixed shapes for this problem instance)
#define NN   50000
#define EE   800000
#define LM   1024
#define HH   128
#define OUTC 64

// ---------------- scratch (static __device__, no allocation) ----------------
__device__ __nv_bfloat16 g_xh [(size_t)NN * LM];   // xout split hi
__device__ __nv_bfloat16 g_xl [(size_t)NN * LM];   // xout split lo
__device__ __nv_bfloat16 g_h1h[(size_t)NN * LM];   // h1 split hi
__device__ __nv_bfloat16 g_h1l[(size_t)NN * LM];   // h1 split lo
__device__ __nv_bfloat16 g_wth [(size_t)LM * LM];  // Wl^T hi   [1024,1024]
__device__ __nv_bfloat16 g_wtl [(size_t)LM * LM];  // Wl^T lo
__device__ __nv_bfloat16 g_w1th[(size_t)HH * LM];  // W1^T hi   [128,1024]
__device__ __nv_bfloat16 g_w1tl[(size_t)HH * LM];  // W1^T lo
__device__ float g_hp1[(size_t)NN * HH];           // h1 @ W1
__device__ float g_h2 [(size_t)NN * HH];           // conv1 output (relu'd)
__device__ float g_hp3[(size_t)NN * OUTC];         // h2 @ W3
__device__ float g_deg [NN];
__device__ float g_dis [NN];
__device__ int   g_cnt [NN];
__device__ int   g_rowptr[NN + 1];
__device__ int   g_bsum[64];
__device__ int   g_csr_src [EE];
__device__ float g_csr_coef[EE];
__device__ int   g_is64;

// ---------------- portable PTX helpers (sm_80+, compile for compute_103) ----
__device__ __forceinline__ uint32_t smem_to_u32(const void* p) {
    uint32_t a;
    asm("{ .reg .u64 t; cvta.to.shared.u64 t, %1; cvt.u32.u64 %0, t; }" : "=r"(a) : "l"(p));
    return a;
}
#define CP_ASYNC16(saddr, gaddr, sz) \
    asm volatile("cp.async.cg.shared.global [%0], [%1], 16, %2;" \
        :: "r"(saddr), "l"(gaddr), "r"(sz))
#define CP_COMMIT() asm volatile("cp.async.commit_group;" ::: "memory")
#define CP_WAIT(n)  asm volatile("cp.async.wait_group %0;" :: "n"(n) : "memory")
#define LDSM_X4(R, ADDR) \
    asm volatile("ldmatrix.sync.aligned.m8n8.x4.shared.b16 {%0,%1,%2,%3}, [%4];" \
        : "=r"((R)[0]), "=r"((R)[1]), "=r"((R)[2]), "=r"((R)[3]) : "r"(ADDR))

__device__ __forceinline__ void mma_bf16(float* d, const uint32_t* a,
                                         uint32_t b0, uint32_t b1) {
    asm volatile(
        "mma.sync.aligned.m16n8k16.row.col.f32.bf16.bf16.f32 "
        "{%0,%1,%2,%3}, {%4,%5,%6,%7}, {%8,%9}, {%0,%1,%2,%3};"
        : "+f"(d[0]), "+f"(d[1]), "+f"(d[2]), "+f"(d[3])
        : "r"(a[0]), "r"(a[1]), "r"(a[2]), "r"(a[3]), "r"(b0), "r"(b1));
}

// ---------------- buffer selectors (avoid host symbol lookups) ----------------
__device__ __forceinline__ float* sel_buf(int SEL, float* p) {
    switch (SEL) {
        case 2: return g_hp1;
        case 3: return g_h2;
        case 4: return g_hp3;
        default: return p;
    }
}
__device__ __forceinline__ const __nv_bfloat16* sel_a(int SEL, int lo) {
    if (SEL == 1) return lo ? g_xl  : g_xh;
    else          return lo ? g_h1l : g_h1h;
}
__device__ __forceinline__ const __nv_bfloat16* sel_b(int SEL, int lo) {
    if (SEL == 1) return lo ? g_wtl  : g_wth;
    else          return lo ? g_w1tl : g_w1th;
}

// edge index fetch honoring detected dtype
__device__ __forceinline__ int edge_at(const void* ei, long long idx) {
    if (g_is64) return (int)((const long long*)ei)[idx];
    return ((const int*)ei)[idx];
}

// ---------------- dtype detection ----------------
__global__ void k_detect(const unsigned int* __restrict__ w) {
    if (threadIdx.x == 0 && blockIdx.x == 0) {
        int is64 = 1;
        for (int i = 1; i < 64; i += 2)
            if (w[i] != 0u) { is64 = 0; break; }
        g_is64 = is64;
    }
}

// ---------------- graph preprocessing ----------------
__global__ void k_init(int n) {
    int i = blockIdx.x * blockDim.x + threadIdx.x;
    if (i < n) { g_deg[i] = 1.0f; g_cnt[i] = 0; }
}

__global__ void k_count(const void* __restrict__ ei, const float* __restrict__ ew, int e_) {
    int e = blockIdx.x * blockDim.x + threadIdx.x;
    if (e >= e_) return;
    int d = edge_at(ei, (long long)e_ + e);
    atomicAdd(&g_deg[d], ew[e]);
    atomicAdd(&g_cnt[d], 1);
}

// multi-block scan, phase A: per-block local exclusive scan + block totals
__global__ void k_scanA(int n) {
    __shared__ int wsum[32];
    int tid  = threadIdx.x;
    int warp = tid >> 5;
    int idx  = blockIdx.x * 1024 + tid;
    int v = (idx < n) ? g_cnt[idx] : 0;
    int inc = v;
    #pragma unroll
    for (int o = 1; o < 32; o <<= 1) {
        int nb = __shfl_up_sync(0xffffffffu, inc, o);
        if ((tid & 31) >= o) inc += nb;
    }
    if ((tid & 31) == 31) wsum[warp] = inc;
    __syncthreads();
    if (tid < 32) {
        int w = wsum[tid];
        #pragma unroll
        for (int o = 1; o < 32; o <<= 1) {
            int nb = __shfl_up_sync(0xffffffffu, w, o);
            if (tid >= o) w += nb;
        }
        wsum[tid] = w;
    }
    __syncthreads();
    int excl = inc - v + ((warp > 0) ? wsum[warp - 1] : 0);
    if (idx < n) {
        g_rowptr[idx] = excl;
        g_cnt[idx]    = 0;
        g_dis[idx]    = rsqrtf(g_deg[idx]);
    }
    if (tid == 0) g_bsum[blockIdx.x] = wsum[31];
}

// phase B: add block offsets (each block redundantly reduces prior block sums)
__global__ void k_scanB(int n, int e_) {
    __shared__ int s_off;
    int tid = threadIdx.x;
    if (tid < 32) {
        int acc = 0;
        for (int i = tid; i < (int)blockIdx.x; i += 32) acc += g_bsum[i];
        #pragma unroll
        for (int o = 16; o > 0; o >>= 1)
            acc += __shfl_down_sync(0xffffffffu, acc, o);
        if (tid == 0) s_off = acc;
    }
    __syncthreads();
    int idx = blockIdx.x * 1024 + tid;
    if (idx < n) g_rowptr[idx] += s_off;
    if (idx == n - 1) g_rowptr[n] = e_;
}

__global__ void k_fill(const void* __restrict__ ei, const float* __restrict__ ew, int e_) {
    int e = blockIdx.x * blockDim.x + threadIdx.x;
    if (e >= e_) return;
    int s = edge_at(ei, e);
    int d = edge_at(ei, (long long)e_ + e);
    int p = g_rowptr[d] + atomicAdd(&g_cnt[d], 1);
    g_csr_src[p]  = s;
    g_csr_coef[p] = g_dis[s] * ew[e] * g_dis[d];
}

// ---------------- bf16 split kernels ----------------
__global__ void k_split_x(const float* __restrict__ src, long long total) {
    long long i = (long long)blockIdx.x * blockDim.x + threadIdx.x;
    if (i >= total) return;
    float v = src[i];
    __nv_bfloat16 h = __float2bfloat16(v);
    g_xh[i] = h;
    g_xl[i] = __float2bfloat16(v - __bfloat162float(h));
}
// W [K=1024, NO] row-major  ->  WT splits [NO, 1024] bf16
template <int WSEL>
__global__ void k_split_wt(const float* __restrict__ W, int NO) {
    int idx = blockIdx.x * blockDim.x + threadIdx.x;
    if (idx >= LM * NO) return;
    int k = idx / NO, nn = idx % NO;
    float v = W[idx];
    __nv_bfloat16 h = __float2bfloat16(v);
    __nv_bfloat16 l = __float2bfloat16(v - __bfloat162float(h));
    __nv_bfloat16* th = (WSEL == 1) ? g_wth : g_w1th;
    __nv_bfloat16* tl = (WSEL == 1) ? g_wtl : g_w1tl;
    th[(size_t)nn * LM + k] = h;
    tl[(size_t)nn * LM + k] = l;
}

// ---------------- mma.sync split-bf16 GEMM ----------------
// D[M, NG] = A[M,1024] @ B^T, A = Ah+Al, B = Bh+Bl, 3 tensor products, fp32 acc.
// Block 128xBN, BK=32, warp tile 32x64, cp.async double buffer.
// EPI=1: v = d + bl + c*Wc + x*Wa, relu, store bf16 splits -> g_h1h/g_h1l (stride LM)
// EPI=0: store fp32 -> g_hp1 (stride HH)
template <int EPI, int ASEL, int BSEL, int BN, int THREADS>
__global__ __launch_bounds__(THREADS)
void k_gemm_mma(int M,
                const float* __restrict__ cvec, const float* __restrict__ xvec,
                const float* __restrict__ Wc,   const float* __restrict__ Wa,
                const float* __restrict__ bl) {
    constexpr int BK  = 32;
    constexpr int NIT = LM / BK;                 // 32
    constexpr int ASZ = 128 * BK * 2;            // 8192 bytes per A half
    constexpr int BSZ = BN * BK * 2;             // bytes per B half
    constexpr int STAGE = 2 * ASZ + 2 * BSZ;

    extern __shared__ char smem[];
    const uint32_t sbase0 = smem_to_u32(smem);

    const int tid    = threadIdx.x;
    const int lane   = tid & 31;
    const int wid    = tid >> 5;
    const int warp_m = wid & 3;                  // 4 warps in M (32 rows each)
    const int warp_n = wid >> 2;                 // BN/64 warps in N (64 cols each)

    const int block_row = blockIdx.y * 128;
    const int block_col = blockIdx.x * BN;

    const __nv_bfloat16* __restrict__ Ah = sel_a(ASEL, 0);
    const __nv_bfloat16* __restrict__ Al = sel_a(ASEL, 1);
    const __nv_bfloat16* __restrict__ Bh = sel_b(BSEL, 0);
    const __nv_bfloat16* __restrict__ Bl = sel_b(BSEL, 1);

    auto issue_tile = [&](int stage, int k0) {
        uint32_t sb = sbase0 + stage * STAGE;
        #pragma unroll
        for (int i = tid; i < 512; i += THREADS) {           // A: 128 rows x 4 chunks
            int r = i >> 2, cb = i & 3;
            uint32_t so = (uint32_t)(r * 64 + ((cb ^ ((r >> 1) & 3)) * 16));
            long long arow = block_row + r;
            size_t ga = (size_t)arow * LM + k0 + cb * 8;
            uint32_t asz = (arow < M) ? 16u : 0u;
            CP_ASYNC16(sb + so,       (const char*)(Ah + ga), asz);
            CP_ASYNC16(sb + ASZ + so, (const char*)(Al + ga), asz);
        }
        #pragma unroll
        for (int i = tid; i < BN * 4; i += THREADS) {        // B: BN rows x 4 chunks
            int r = i >> 2, cb = i & 3;
            uint32_t so = (uint32_t)(r * 64 + ((cb ^ ((r >> 1) & 3)) * 16));
            size_t gb = (size_t)(block_col + r) * LM + k0 + cb * 8;
            CP_ASYNC16(sb + 2 * ASZ + so,       (const char*)(Bh + gb), 16u);
            CP_ASYNC16(sb + 2 * ASZ + BSZ + so, (const char*)(Bl + gb), 16u);
        }
        CP_COMMIT();
    };

    float acc[2][8][4];
    #pragma unroll
    for (int i = 0; i < 2; i++)
        #pragma unroll
        for (int j = 0; j < 8; j++)
            #pragma unroll
            for (int q = 0; q < 4; q++) acc[i][j][q] = 0.0f;

    issue_tile(0, 0);

    for (int it = 0; it < NIT; it++) {
        if (it + 1 < NIT) {
            issue_tile((it + 1) & 1, (it + 1) * BK);
            CP_WAIT(1);
        } else {
            CP_WAIT(0);
        }
        __syncthreads();

        const uint32_t sb = sbase0 + (it & 1) * STAGE;
        #pragma unroll
        for (int ks = 0; ks < 2; ks++) {
            uint32_t aH[2][4], aL[2][4];
            #pragma unroll
            for (int mt = 0; mt < 2; mt++) {
                int row = warp_m * 32 + mt * 16 + (lane & 15);
                int cb  = ks * 2 + (lane >> 4);
                uint32_t off = (uint32_t)(row * 64 + ((cb ^ ((row >> 1) & 3)) * 16));
                LDSM_X4(aH[mt], sb + off);
                LDSM_X4(aL[mt], sb + ASZ + off);
            }
            #pragma unroll
            for (int g = 0; g < 4; g++) {
                uint32_t bh[4], blr[4];
                int row = warp_n * 64 + g * 16 + (lane & 15);
                int cb  = ks * 2 + (lane >> 4);
                uint32_t off = (uint32_t)(row * 64 + ((cb ^ ((row >> 1) & 3)) * 16));
                LDSM_X4(bh,  sb + 2 * ASZ + off);
                LDSM_X4(blr, sb + 2 * ASZ + BSZ + off);
                #pragma unroll
                for (int mt = 0; mt < 2; mt++) {
                    #pragma unroll
                    for (int sub = 0; sub < 2; sub++) {
                        int nt = g * 2 + sub;
                        mma_bf16(acc[mt][nt], aH[mt], bh[sub],  bh[sub + 2]);   // hi*hi
                        mma_bf16(acc[mt][nt], aH[mt], blr[sub], blr[sub + 2]);  // hi*lo
                        mma_bf16(acc[mt][nt], aL[mt], bh[sub],  bh[sub + 2]);   // lo*hi
                    }
                }
            }
        }
        __syncthreads();
    }

    // ---------------- epilogue ----------------
    #pragma unroll
    for (int nt = 0; nt < 8; nt++) {
        int col = block_col + warp_n * 64 + nt * 8 + (lane & 3) * 2;
        float bl0 = 0.f, bl1 = 0.f, wc0 = 0.f, wc1 = 0.f, wa0 = 0.f, wa1 = 0.f;
        if (EPI == 1) {
            bl0 = bl[col];  bl1 = bl[col + 1];
            wc0 = Wc[col];  wc1 = Wc[col + 1];
            wa0 = Wa[col];  wa1 = Wa[col + 1];
        }
        #pragma unroll
        for (int mt = 0; mt < 2; mt++) {
            int rbase = block_row + warp_m * 32 + mt * 16 + (lane >> 2);
            #pragma unroll
            for (int h = 0; h < 2; h++) {
                int row = rbase + h * 8;
                if (row >= M) continue;
                float v0 = acc[mt][nt][h * 2 + 0];
                float v1 = acc[mt][nt][h * 2 + 1];
                if (EPI == 1) {
                    float cv = cvec[row], xv = xvec[row];
                    v0 = fmaxf(v0 + bl0 + cv * wc0 + xv * wa0, 0.f);
                    v1 = fmaxf(v1 + bl1 + cv * wc1 + xv * wa1, 0.f);
                    __nv_bfloat16 h0 = __float2bfloat16(v0);
                    __nv_bfloat16 h1 = __float2bfloat16(v1);
                    __nv_bfloat162 hh; hh.x = h0; hh.y = h1;
                    __nv_bfloat162 ll;
                    ll.x = __float2bfloat16(v0 - __bfloat162float(h0));
                    ll.y = __float2bfloat16(v1 - __bfloat162float(h1));
                    *(__nv_bfloat162*)&g_h1h[(size_t)row * LM + col] = hh;
                    *(__nv_bfloat162*)&g_h1l[(size_t)row * LM + col] = ll;
                } else {
                    float2 f2; f2.x = v0; f2.y = v1;
                    *(float2*)&g_hp1[(size_t)row * HH + col] = f2;
                }
            }
        }
    }
}

// ---------------- SIMT GEMM (small conv3 projection) ----------------
template <int BM, int BN, int BK, int TM, int TN, int ASEL, int DSEL>
__global__ __launch_bounds__((BM / TM) * (BN / TN))
void k_gemm(const float* __restrict__ Ap, const float* __restrict__ B,
            float* __restrict__ Cp, int M, int N, int K) {
    const float* __restrict__ A = sel_buf(ASEL, (float*)Ap);
    float* __restrict__ C = sel_buf(DSEL, Cp);

    constexpr int THREADS = (BM / TM) * (BN / TN);
    __shared__ float As[BK][BM];
    __shared__ float Bs[BK][BN];

    const int block_row = blockIdx.y * BM;
    const int block_col = blockIdx.x * BN;
    const int tid  = threadIdx.x;
    const int tcol = tid % (BN / TN);
    const int trow = tid / (BN / TN);

    float acc[TM][TN];
    #pragma unroll
    for (int i = 0; i < TM; i++)
        #pragma unroll
        for (int j = 0; j < TN; j++) acc[i][j] = 0.0f;

    for (int k0 = 0; k0 < K; k0 += BK) {
        #pragma unroll
        for (int i = tid; i < BM * BK / 4; i += THREADS) {
            int r  = i / (BK / 4);
            int c4 = i % (BK / 4);
            int grow = block_row + r;
            float4 v = (grow < M)
                ? *(const float4*)&A[(size_t)grow * K + k0 + c4 * 4]
                : make_float4(0.f, 0.f, 0.f, 0.f);
            As[c4 * 4 + 0][r] = v.x;
            As[c4 * 4 + 1][r] = v.y;
            As[c4 * 4 + 2][r] = v.z;
            As[c4 * 4 + 3][r] = v.w;
        }
        #pragma unroll
        for (int i = tid; i < BK * BN / 4; i += THREADS) {
            int r  = i / (BN / 4);
            int c4 = i % (BN / 4);
            *(float4*)&Bs[r][c4 * 4] =
                *(const float4*)&B[(size_t)(k0 + r) * N + block_col + c4 * 4];
        }
        __syncthreads();
        #pragma unroll
        for (int k = 0; k < BK; k++) {
            float a[TM], b[TN];
            #pragma unroll
            for (int i = 0; i < TM; i++) a[i] = As[k][trow * TM + i];
            #pragma unroll
            for (int j = 0; j < TN; j++) b[j] = Bs[k][tcol * TN + j];
            #pragma unroll
            for (int i = 0; i < TM; i++)
                #pragma unroll
                for (int j = 0; j < TN; j++)
                    acc[i][j] = fmaf(a[i], b[j], acc[i][j]);
        }
        __syncthreads();
    }
    #pragma unroll
    for (int i = 0; i < TM; i++) {
        int grow = block_row + trow * TM + i;
        if (grow >= M) continue;
        #pragma unroll
        for (int j = 0; j < TN; j++) {
            int gcol = block_col + tcol * TN + j;
            C[(size_t)grow * N + gcol] = acc[i][j];
        }
    }
}

// ---------------- GCN aggregation (CSR gather, warp per node) ----------------
template <int F, bool RELU, int HPSEL, int OSEL>
__global__ void k_agg(const float* __restrict__ bias, float* __restrict__ outp, int n) {
    const float* __restrict__ hp = sel_buf(HPSEL, nullptr);
    float* __restrict__ out = sel_buf(OSEL, outp);

    int warp = (blockIdx.x * blockDim.x + threadIdx.x) >> 5;
    int lane = threadIdx.x & 31;
    if (warp >= n) return;
    const int node = warp;
    constexpr int V = F / 32;
    float acc[V];

    float selfc = g_dis[node] * g_dis[node];
    const float* hrow = hp + (size_t)node * F + lane * V;
    #pragma unroll
    for (int j = 0; j < V; j++) acc[j] = selfc * hrow[j];

    int beg = g_rowptr[node];
    int end = g_rowptr[node + 1];
    for (int e = beg; e < end; e++) {
        int   s  = g_csr_src[e];
        float cf = g_csr_coef[e];
        const float* srow = hp + (size_t)s * F + lane * V;
        if (V == 4) {
            float4 v = *(const float4*)srow;
            acc[0] = fmaf(cf, v.x, acc[0]);
            acc[1] = fmaf(cf, v.y, acc[1]);
            acc[2] = fmaf(cf, v.z, acc[2]);
            acc[3] = fmaf(cf, v.w, acc[3]);
        } else {
            float2 v = *(const float2*)srow;
            acc[0] = fmaf(cf, v.x, acc[0]);
            acc[1] = fmaf(cf, v.y, acc[1]);
        }
    }
    #pragma unroll
    for (int j = 0; j < V; j++) {
        float v = acc[j] + bias[lane * V + j];
        if (RELU) v = fmaxf(v, 0.f);
        out[(size_t)node * F + lane * V + j] = v;
    }
}

// ---------------- launch ----------------
extern "C" void kernel_launch(void* const* d_in, const int* in_sizes, int n_in,
                              void* d_out, int out_size) {
    const float* x    = (const float*)d_in[0];
    const float* xout = (const float*)d_in[1];
    const float* c    = (const float*)d_in[2];
    const void*  ei   = d_in[3];
    const float* ew   = (const float*)d_in[4];
    const float* Wa   = (const float*)d_in[5];
    const float* Wc   = (const float*)d_in[6];
    const float* Wl   = (const float*)d_in[7];
    const float* bl   = (const float*)d_in[8];
    const float* W1   = (const float*)d_in[9];
    const float* b1   = (const float*)d_in[10];
    const float* W3   = (const float*)d_in[11];
    const float* b3   = (const float*)d_in[12];
    float* out = (float*)d_out;

    const int n = in_sizes[0];
    const int e = in_sizes[3] / 2;

    // GEMM1: BN=256, STAGE = 2*8192 + 2*16384 = 48KB, x2 stages = 96KB
    const int SMEM_G1 = 2 * (2 * 8192 + 2 * 256 * 32 * 2);
    // GEMM2: BN=128, STAGE = 2*8192 + 2*8192 = 32KB, x2 stages = 64KB
    const int SMEM_G2 = 2 * (2 * 8192 + 2 * 128 * 32 * 2);
    cudaFuncSetAttribute(k_gemm_mma<1, 1, 1, 256, 512>,
                         cudaFuncAttributeMaxDynamicSharedMemorySize, SMEM_G1);
    cudaFuncSetAttribute(k_gemm_mma<0, 2, 2, 128, 256>,
                         cudaFuncAttributeMaxDynamicSharedMemorySize, SMEM_G2);

    // --- dtype detection + graph preprocessing ---
    const int nblk = (n + 1023) / 1024;
    k_detect<<<1, 32>>>((const unsigned int*)ei);
    k_init  <<<(n + 255) / 256, 256>>>(n);
    k_count <<<(e + 255) / 256, 256>>>(ei, ew, e);
    k_scanA <<<nblk, 1024>>>(n);
    k_scanB <<<nblk, 1024>>>(n, e);
    k_fill  <<<(e + 255) / 256, 256>>>(ei, ew, e);

    // --- bf16 splits: xout, Wl^T, W1^T ---
    {
        long long tot = (long long)n * LM;
        k_split_x<<<(unsigned)((tot + 511) / 512), 512>>>(xout, tot);
        k_split_wt<1><<<(LM * LM + 255) / 256, 256>>>(Wl, LM);
        k_split_wt<2><<<(LM * HH + 255) / 256, 256>>>(W1, HH);
    }

    // --- layer 0 (mma.sync, 128x256 tile): h1 splits = relu(xout @ Wl + epi) ---
    {
        dim3 grid(LM / 256, (n + 127) / 128);
        k_gemm_mma<1, 1, 1, 256, 512><<<grid, 512, SMEM_G1>>>(n, c, x, Wc, Wa, bl);
    }
    // --- conv1 projection (mma.sync): g_hp1 = h1 @ W1 ---
    {
        dim3 grid(HH / 128, (n + 127) / 128);
        k_gemm_mma<0, 2, 2, 128, 256><<<grid, 256, SMEM_G2>>>(n, nullptr, nullptr, nullptr, nullptr, nullptr);
    }
    // --- conv1 aggregation + bias + relu: g_h2 ---
    k_agg<HH, true, 2, 3><<<(n * 32 + 255) / 256, 256>>>(b1, nullptr, n);

    // --- conv3 projection (SIMT): g_hp3 = g_h2 @ W3 ---
    {
        dim3 grid(OUTC / 64, (n + 127) / 128);
        k_gemm<128, 64, 16, 8, 4, 3, 4><<<grid, 256>>>(nullptr, W3, nullptr, n, OUTC, HH);
    }
    // --- conv3 aggregation + bias: out ---
    k_agg<OUTC, false, 4, 0><<<(n * 32 + 255) / 256, 256>>>(b3, out, n);
}

// round 9
// speedup vs baseline: 1.1170x; 1.1170x over previous
#include <cuda_runtime.h>
#include <cuda_bf16.h>
#include <cstdint>

// Problem constants (fixed shapes for this problem instance)
#define NN   50000
#define EE   800000
#define LM   1024
#define HH   128
#define OUTC 64

// ---------------- scratch (static __device__, no allocation) ----------------
__device__ __nv_bfloat16 g_xh [(size_t)NN * LM];   // xout split hi
__device__ __nv_bfloat16 g_xl [(size_t)NN * LM];   // xout split lo
__device__ __nv_bfloat16 g_h1h[(size_t)NN * LM];   // h1 split hi
__device__ __nv_bfloat16 g_h1l[(size_t)NN * LM];   // h1 split lo
__device__ __nv_bfloat16 g_wth [(size_t)LM * LM];  // Wl^T hi   [1024,1024]
__device__ __nv_bfloat16 g_wtl [(size_t)LM * LM];  // Wl^T lo
__device__ __nv_bfloat16 g_w1th[(size_t)HH * LM];  // W1^T hi   [128,1024]
__device__ __nv_bfloat16 g_w1tl[(size_t)HH * LM];  // W1^T lo
__device__ float g_hp1[(size_t)NN * HH];           // h1 @ W1
__device__ float g_h2 [(size_t)NN * HH];           // conv1 output (relu'd)
__device__ float g_hp3[(size_t)NN * OUTC];         // h2 @ W3
__device__ float g_deg [NN];
__device__ float g_dis [NN];
__device__ int   g_cnt [NN];
__device__ int   g_rowptr[NN + 1];
__device__ int   g_bsum[64];
__device__ int   g_csr_src [EE];
__device__ float g_csr_coef[EE];
__device__ int   g_is64;

// ---------------- portable PTX helpers (sm_80+, compile for compute_103) ----
__device__ __forceinline__ uint32_t smem_to_u32(const void* p) {
    uint32_t a;
    asm("{ .reg .u64 t; cvta.to.shared.u64 t, %1; cvt.u32.u64 %0, t; }" : "=r"(a) : "l"(p));
    return a;
}
#define CP_ASYNC16(saddr, gaddr, sz) \
    asm volatile("cp.async.cg.shared.global [%0], [%1], 16, %2;" \
        :: "r"(saddr), "l"(gaddr), "r"(sz))
#define CP_COMMIT() asm volatile("cp.async.commit_group;" ::: "memory")
#define CP_WAIT(n)  asm volatile("cp.async.wait_group %0;" :: "n"(n) : "memory")
#define LDSM_X4(R, ADDR) \
    asm volatile("ldmatrix.sync.aligned.m8n8.x4.shared.b16 {%0,%1,%2,%3}, [%4];" \
        : "=r"((R)[0]), "=r"((R)[1]), "=r"((R)[2]), "=r"((R)[3]) : "r"(ADDR))

__device__ __forceinline__ void mma_bf16(float* d, const uint32_t* a,
                                         uint32_t b0, uint32_t b1) {
    asm volatile(
        "mma.sync.aligned.m16n8k16.row.col.f32.bf16.bf16.f32 "
        "{%0,%1,%2,%3}, {%4,%5,%6,%7}, {%8,%9}, {%0,%1,%2,%3};"
        : "+f"(d[0]), "+f"(d[1]), "+f"(d[2]), "+f"(d[3])
        : "r"(a[0]), "r"(a[1]), "r"(a[2]), "r"(a[3]), "r"(b0), "r"(b1));
}

// ---------------- buffer selectors (avoid host symbol lookups) ----------------
__device__ __forceinline__ float* sel_buf(int SEL, float* p) {
    switch (SEL) {
        case 2: return g_hp1;
        case 3: return g_h2;
        case 4: return g_hp3;
        default: return p;
    }
}
__device__ __forceinline__ const __nv_bfloat16* sel_a(int SEL, int lo) {
    if (SEL == 1) return lo ? g_xl  : g_xh;
    else          return lo ? g_h1l : g_h1h;
}
__device__ __forceinline__ const __nv_bfloat16* sel_b(int SEL, int lo) {
    if (SEL == 1) return lo ? g_wtl  : g_wth;
    else          return lo ? g_w1tl : g_w1th;
}

// edge index fetch honoring detected dtype
__device__ __forceinline__ int edge_at(const void* ei, long long idx) {
    if (g_is64) return (int)((const long long*)ei)[idx];
    return ((const int*)ei)[idx];
}

// ---------------- dtype detection ----------------
__global__ void k_detect(const unsigned int* __restrict__ w) {
    if (threadIdx.x == 0 && blockIdx.x == 0) {
        int is64 = 1;
        for (int i = 1; i < 64; i += 2)
            if (w[i] != 0u) { is64 = 0; break; }
        g_is64 = is64;
    }
}

// ---------------- graph preprocessing ----------------
__global__ void k_init(int n) {
    int i = blockIdx.x * blockDim.x + threadIdx.x;
    if (i < n) { g_deg[i] = 1.0f; g_cnt[i] = 0; }
}

__global__ void k_count(const void* __restrict__ ei, const float* __restrict__ ew, int e_) {
    int e = blockIdx.x * blockDim.x + threadIdx.x;
    if (e >= e_) return;
    int d = edge_at(ei, (long long)e_ + e);
    atomicAdd(&g_deg[d], ew[e]);
    atomicAdd(&g_cnt[d], 1);
}

// multi-block scan, phase A: per-block local exclusive scan + block totals
__global__ void k_scanA(int n) {
    __shared__ int wsum[32];
    int tid  = threadIdx.x;
    int warp = tid >> 5;
    int idx  = blockIdx.x * 1024 + tid;
    int v = (idx < n) ? g_cnt[idx] : 0;
    int inc = v;
    #pragma unroll
    for (int o = 1; o < 32; o <<= 1) {
        int nb = __shfl_up_sync(0xffffffffu, inc, o);
        if ((tid & 31) >= o) inc += nb;
    }
    if ((tid & 31) == 31) wsum[warp] = inc;
    __syncthreads();
    if (tid < 32) {
        int w = wsum[tid];
        #pragma unroll
        for (int o = 1; o < 32; o <<= 1) {
            int nb = __shfl_up_sync(0xffffffffu, w, o);
            if (tid >= o) w += nb;
        }
        wsum[tid] = w;
    }
    __syncthreads();
    int excl = inc - v + ((warp > 0) ? wsum[warp - 1] : 0);
    if (idx < n) {
        g_rowptr[idx] = excl;
        g_cnt[idx]    = 0;
        g_dis[idx]    = rsqrtf(g_deg[idx]);
    }
    if (tid == 0) g_bsum[blockIdx.x] = wsum[31];
}

// phase B: add block offsets (each block redundantly reduces prior block sums)
__global__ void k_scanB(int n, int e_) {
    __shared__ int s_off;
    int tid = threadIdx.x;
    if (tid < 32) {
        int acc = 0;
        for (int i = tid; i < (int)blockIdx.x; i += 32) acc += g_bsum[i];
        #pragma unroll
        for (int o = 16; o > 0; o >>= 1)
            acc += __shfl_down_sync(0xffffffffu, acc, o);
        if (tid == 0) s_off = acc;
    }
    __syncthreads();
    int idx = blockIdx.x * 1024 + tid;
    if (idx < n) g_rowptr[idx] += s_off;
    if (idx == n - 1) g_rowptr[n] = e_;
}

__global__ void k_fill(const void* __restrict__ ei, const float* __restrict__ ew, int e_) {
    int e = blockIdx.x * blockDim.x + threadIdx.x;
    if (e >= e_) return;
    int s = edge_at(ei, e);
    int d = edge_at(ei, (long long)e_ + e);
    int p = g_rowptr[d] + atomicAdd(&g_cnt[d], 1);
    g_csr_src[p]  = s;
    g_csr_coef[p] = g_dis[s] * ew[e] * g_dis[d];
}

// ---------------- bf16 split kernels ----------------
__global__ void k_split_x(const float* __restrict__ src, long long total) {
    long long i = (long long)blockIdx.x * blockDim.x + threadIdx.x;
    if (i >= total) return;
    float v = src[i];
    __nv_bfloat16 h = __float2bfloat16(v);
    g_xh[i] = h;
    g_xl[i] = __float2bfloat16(v - __bfloat162float(h));
}
// W [K=1024, NO] row-major  ->  WT splits [NO, 1024] bf16
template <int WSEL>
__global__ void k_split_wt(const float* __restrict__ W, int NO) {
    int idx = blockIdx.x * blockDim.x + threadIdx.x;
    if (idx >= LM * NO) return;
    int k = idx / NO, nn = idx % NO;
    float v = W[idx];
    __nv_bfloat16 h = __float2bfloat16(v);
    __nv_bfloat16 l = __float2bfloat16(v - __bfloat162float(h));
    __nv_bfloat16* th = (WSEL == 1) ? g_wth : g_w1th;
    __nv_bfloat16* tl = (WSEL == 1) ? g_wtl : g_w1tl;
    th[(size_t)nn * LM + k] = h;
    tl[(size_t)nn * LM + k] = l;
}

// ---------------- mma.sync split-bf16 GEMM ----------------
// D[M, NG] = A[M,1024] @ B^T, A = Ah+Al, B = Bh+Bl, 3 tensor products, fp32 acc.
// Block 128x128, BK=32, 8 warps (warp tile 32x64), cp.async 3-stage pipeline.
// EPI=1: v = d + bl + c*Wc + x*Wa, relu, store bf16 splits -> g_h1h/g_h1l (stride LM)
// EPI=0: store fp32 -> g_hp1 (stride HH)
template <int EPI, int ASEL, int BSEL>
__global__ __launch_bounds__(256)
void k_gemm_mma(int M,
                const float* __restrict__ cvec, const float* __restrict__ xvec,
                const float* __restrict__ Wc,   const float* __restrict__ Wa,
                const float* __restrict__ bl) {
    constexpr int BK  = 32;
    constexpr int NIT = LM / BK;            // 32
    constexpr int STAGE = 32768;            // Ah 8K | Al 8K | Bh 8K | Bl 8K
    constexpr int NSTAGE = 3;

    extern __shared__ char smem[];
    const uint32_t sbase0 = smem_to_u32(smem);

    const int tid    = threadIdx.x;
    const int lane   = tid & 31;
    const int wid    = tid >> 5;
    const int warp_m = wid & 3;             // 4 warps in M (32 rows each)
    const int warp_n = wid >> 2;            // 2 warps in N (64 cols each)

    const int block_row = blockIdx.y * 128;
    const int block_col = blockIdx.x * 128;

    const __nv_bfloat16* __restrict__ Ah = sel_a(ASEL, 0);
    const __nv_bfloat16* __restrict__ Al = sel_a(ASEL, 1);
    const __nv_bfloat16* __restrict__ Bh = sel_b(BSEL, 0);
    const __nv_bfloat16* __restrict__ Bl = sel_b(BSEL, 1);

    // per-thread load slots: idx -> (row = idx>>2, 16B chunk = idx&3)
    const int r0  = tid >> 2,            cb0 = tid & 3;
    const int r1  = (tid + 256) >> 2,    cb1 = tid & 3;
    const uint32_t so0 = (uint32_t)(r0 * 64 + ((cb0 ^ ((r0 >> 1) & 3)) * 16));
    const uint32_t so1 = (uint32_t)(r1 * 64 + ((cb1 ^ ((r1 >> 1) & 3)) * 16));

    auto issue_tile = [&](int stage, int k0) {
        uint32_t sb = sbase0 + stage * STAGE;
        {
            long long arow = block_row + r0;
            size_t ga = (size_t)arow * LM + k0 + cb0 * 8;
            uint32_t asz = (arow < M) ? 16u : 0u;
            CP_ASYNC16(sb + so0,         (const char*)(Ah + ga), asz);
            CP_ASYNC16(sb + 8192 + so0,  (const char*)(Al + ga), asz);
            size_t gb = (size_t)(block_col + r0) * LM + k0 + cb0 * 8;
            CP_ASYNC16(sb + 16384 + so0, (const char*)(Bh + gb), 16u);
            CP_ASYNC16(sb + 24576 + so0, (const char*)(Bl + gb), 16u);
        }
        {
            long long arow = block_row + r1;
            size_t ga = (size_t)arow * LM + k0 + cb1 * 8;
            uint32_t asz = (arow < M) ? 16u : 0u;
            CP_ASYNC16(sb + so1,         (const char*)(Ah + ga), asz);
            CP_ASYNC16(sb + 8192 + so1,  (const char*)(Al + ga), asz);
            size_t gb = (size_t)(block_col + r1) * LM + k0 + cb1 * 8;
            CP_ASYNC16(sb + 16384 + so1, (const char*)(Bh + gb), 16u);
            CP_ASYNC16(sb + 24576 + so1, (const char*)(Bl + gb), 16u);
        }
        CP_COMMIT();
    };

    float acc[2][8][4];
    #pragma unroll
    for (int i = 0; i < 2; i++)
        #pragma unroll
        for (int j = 0; j < 8; j++)
            #pragma unroll
            for (int q = 0; q < 4; q++) acc[i][j][q] = 0.0f;

    issue_tile(0, 0);
    issue_tile(1, BK);

    int stage = 0;
    for (int it = 0; it < NIT; it++) {
        if (it + 2 < NIT) {
            issue_tile((it + 2) % NSTAGE, (it + 2) * BK);
            CP_WAIT(2);
        } else {
            CP_WAIT(0);
        }
        __syncthreads();

        const uint32_t sb = sbase0 + stage * STAGE;
        #pragma unroll
        for (int ks = 0; ks < 2; ks++) {
            uint32_t aH[2][4], aL[2][4];
            #pragma unroll
            for (int mt = 0; mt < 2; mt++) {
                int row = warp_m * 32 + mt * 16 + (lane & 15);
                int cb  = ks * 2 + (lane >> 4);
                uint32_t off = (uint32_t)(row * 64 + ((cb ^ ((row >> 1) & 3)) * 16));
                LDSM_X4(aH[mt], sb + off);
                LDSM_X4(aL[mt], sb + 8192 + off);
            }
            #pragma unroll
            for (int g = 0; g < 4; g++) {
                uint32_t bh[4], blr[4];
                int row = warp_n * 64 + g * 16 + (lane & 15);
                int cb  = ks * 2 + (lane >> 4);
                uint32_t off = (uint32_t)(row * 64 + ((cb ^ ((row >> 1) & 3)) * 16));
                LDSM_X4(bh,  sb + 16384 + off);
                LDSM_X4(blr, sb + 24576 + off);
                #pragma unroll
                for (int mt = 0; mt < 2; mt++) {
                    #pragma unroll
                    for (int sub = 0; sub < 2; sub++) {
                        int nt = g * 2 + sub;
                        mma_bf16(acc[mt][nt], aH[mt], bh[sub],  bh[sub + 2]);   // hi*hi
                        mma_bf16(acc[mt][nt], aH[mt], blr[sub], blr[sub + 2]);  // hi*lo
                        mma_bf16(acc[mt][nt], aL[mt], bh[sub],  bh[sub + 2]);   // lo*hi
                    }
                }
            }
        }
        __syncthreads();
        stage = (stage + 1 == NSTAGE) ? 0 : stage + 1;
    }

    // ---------------- epilogue ----------------
    #pragma unroll
    for (int nt = 0; nt < 8; nt++) {
        int col = block_col + warp_n * 64 + nt * 8 + (lane & 3) * 2;
        float bl0 = 0.f, bl1 = 0.f, wc0 = 0.f, wc1 = 0.f, wa0 = 0.f, wa1 = 0.f;
        if (EPI == 1) {
            bl0 = bl[col];  bl1 = bl[col + 1];
            wc0 = Wc[col];  wc1 = Wc[col + 1];
            wa0 = Wa[col];  wa1 = Wa[col + 1];
        }
        #pragma unroll
        for (int mt = 0; mt < 2; mt++) {
            int rbase = block_row + warp_m * 32 + mt * 16 + (lane >> 2);
            #pragma unroll
            for (int h = 0; h < 2; h++) {
                int row = rbase + h * 8;
                if (row >= M) continue;
                float v0 = acc[mt][nt][h * 2 + 0];
                float v1 = acc[mt][nt][h * 2 + 1];
                if (EPI == 1) {
                    float cv = cvec[row], xv = xvec[row];
                    v0 = fmaxf(v0 + bl0 + cv * wc0 + xv * wa0, 0.f);
                    v1 = fmaxf(v1 + bl1 + cv * wc1 + xv * wa1, 0.f);
                    __nv_bfloat16 h0 = __float2bfloat16(v0);
                    __nv_bfloat16 h1 = __float2bfloat16(v1);
                    __nv_bfloat162 hh; hh.x = h0; hh.y = h1;
                    __nv_bfloat162 ll;
                    ll.x = __float2bfloat16(v0 - __bfloat162float(h0));
                    ll.y = __float2bfloat16(v1 - __bfloat162float(h1));
                    *(__nv_bfloat162*)&g_h1h[(size_t)row * LM + col] = hh;
                    *(__nv_bfloat162*)&g_h1l[(size_t)row * LM + col] = ll;
                } else {
                    float2 f2; f2.x = v0; f2.y = v1;
                    *(float2*)&g_hp1[(size_t)row * HH + col] = f2;
                }
            }
        }
    }
}

// ---------------- SIMT GEMM (small conv3 projection) ----------------
template <int BM, int BN, int BK, int TM, int TN, int ASEL, int DSEL>
__global__ __launch_bounds__((BM / TM) * (BN / TN))
void k_gemm(const float* __restrict__ Ap, const float* __restrict__ B,
            float* __restrict__ Cp, int M, int N, int K) {
    const float* __restrict__ A = sel_buf(ASEL, (float*)Ap);
    float* __restrict__ C = sel_buf(DSEL, Cp);

    constexpr int THREADS = (BM / TM) * (BN / TN);
    __shared__ float As[BK][BM];
    __shared__ float Bs[BK][BN];

    const int block_row = blockIdx.y * BM;
    const int block_col = blockIdx.x * BN;
    const int tid  = threadIdx.x;
    const int tcol = tid % (BN / TN);
    const int trow = tid / (BN / TN);

    float acc[TM][TN];
    #pragma unroll
    for (int i = 0; i < TM; i++)
        #pragma unroll
        for (int j = 0; j < TN; j++) acc[i][j] = 0.0f;

    for (int k0 = 0; k0 < K; k0 += BK) {
        #pragma unroll
        for (int i = tid; i < BM * BK / 4; i += THREADS) {
            int r  = i / (BK / 4);
            int c4 = i % (BK / 4);
            int grow = block_row + r;
            float4 v = (grow < M)
                ? *(const float4*)&A[(size_t)grow * K + k0 + c4 * 4]
                : make_float4(0.f, 0.f, 0.f, 0.f);
            As[c4 * 4 + 0][r] = v.x;
            As[c4 * 4 + 1][r] = v.y;
            As[c4 * 4 + 2][r] = v.z;
            As[c4 * 4 + 3][r] = v.w;
        }
        #pragma unroll
        for (int i = tid; i < BK * BN / 4; i += THREADS) {
            int r  = i / (BN / 4);
            int c4 = i % (BN / 4);
            *(float4*)&Bs[r][c4 * 4] =
                *(const float4*)&B[(size_t)(k0 + r) * N + block_col + c4 * 4];
        }
        __syncthreads();
        #pragma unroll
        for (int k = 0; k < BK; k++) {
            float a[TM], b[TN];
            #pragma unroll
            for (int i = 0; i < TM; i++) a[i] = As[k][trow * TM + i];
            #pragma unroll
            for (int j = 0; j < TN; j++) b[j] = Bs[k][tcol * TN + j];
            #pragma unroll
            for (int i = 0; i < TM; i++)
                #pragma unroll
                for (int j = 0; j < TN; j++)
                    acc[i][j] = fmaf(a[i], b[j], acc[i][j]);
        }
        __syncthreads();
    }
    #pragma unroll
    for (int i = 0; i < TM; i++) {
        int grow = block_row + trow * TM + i;
        if (grow >= M) continue;
        #pragma unroll
        for (int j = 0; j < TN; j++) {
            int gcol = block_col + tcol * TN + j;
            C[(size_t)grow * N + gcol] = acc[i][j];
        }
    }
}

// ---------------- GCN aggregation (CSR gather, warp per node) ----------------
template <int F, bool RELU, int HPSEL, int OSEL>
__global__ void k_agg(const float* __restrict__ bias, float* __restrict__ outp, int n) {
    const float* __restrict__ hp = sel_buf(HPSEL, nullptr);
    float* __restrict__ out = sel_buf(OSEL, outp);

    int warp = (blockIdx.x * blockDim.x + threadIdx.x) >> 5;
    int lane = threadIdx.x & 31;
    if (warp >= n) return;
    const int node = warp;
    constexpr int V = F / 32;
    float acc[V];

    float selfc = g_dis[node] * g_dis[node];
    const float* hrow = hp + (size_t)node * F + lane * V;
    #pragma unroll
    for (int j = 0; j < V; j++) acc[j] = selfc * hrow[j];

    int beg = g_rowptr[node];
    int end = g_rowptr[node + 1];
    for (int e = beg; e < end; e++) {
        int   s  = g_csr_src[e];
        float cf = g_csr_coef[e];
        const float* srow = hp + (size_t)s * F + lane * V;
        if (V == 4) {
            float4 v = *(const float4*)srow;
            acc[0] = fmaf(cf, v.x, acc[0]);
            acc[1] = fmaf(cf, v.y, acc[1]);
            acc[2] = fmaf(cf, v.z, acc[2]);
            acc[3] = fmaf(cf, v.w, acc[3]);
        } else {
            float2 v = *(const float2*)srow;
            acc[0] = fmaf(cf, v.x, acc[0]);
            acc[1] = fmaf(cf, v.y, acc[1]);
        }
    }
    #pragma unroll
    for (int j = 0; j < V; j++) {
        float v = acc[j] + bias[lane * V + j];
        if (RELU) v = fmaxf(v, 0.f);
        out[(size_t)node * F + lane * V + j] = v;
    }
}

// ---------------- launch ----------------
extern "C" void kernel_launch(void* const* d_in, const int* in_sizes, int n_in,
                              void* d_out, int out_size) {
    const float* x    = (const float*)d_in[0];
    const float* xout = (const float*)d_in[1];
    const float* c    = (const float*)d_in[2];
    const void*  ei   = d_in[3];
    const float* ew   = (const float*)d_in[4];
    const float* Wa   = (const float*)d_in[5];
    const float* Wc   = (const float*)d_in[6];
    const float* Wl   = (const float*)d_in[7];
    const float* bl   = (const float*)d_in[8];
    const float* W1   = (const float*)d_in[9];
    const float* b1   = (const float*)d_in[10];
    const float* W3   = (const float*)d_in[11];
    const float* b3   = (const float*)d_in[12];
    float* out = (float*)d_out;

    const int n = in_sizes[0];
    const int e = in_sizes[3] / 2;

    const int SMEM_MMA = 3 * 32768;   // 96 KB dynamic (3 stages)
    cudaFuncSetAttribute(k_gemm_mma<1, 1, 1>,
                         cudaFuncAttributeMaxDynamicSharedMemorySize, SMEM_MMA);
    cudaFuncSetAttribute(k_gemm_mma<0, 2, 2>,
                         cudaFuncAttributeMaxDynamicSharedMemorySize, SMEM_MMA);

    // --- dtype detection + graph preprocessing ---
    const int nblk = (n + 1023) / 1024;
    k_detect<<<1, 32>>>((const unsigned int*)ei);
    k_init  <<<(n + 255) / 256, 256>>>(n);
    k_count <<<(e + 255) / 256, 256>>>(ei, ew, e);
    k_scanA <<<nblk, 1024>>>(n);
    k_scanB <<<nblk, 1024>>>(n, e);
    k_fill  <<<(e + 255) / 256, 256>>>(ei, ew, e);

    // --- bf16 splits: xout, Wl^T, W1^T ---
    {
        long long tot = (long long)n * LM;
        k_split_x<<<(unsigned)((tot + 511) / 512), 512>>>(xout, tot);
        k_split_wt<1><<<(LM * LM + 255) / 256, 256>>>(Wl, LM);
        k_split_wt<2><<<(LM * HH + 255) / 256, 256>>>(W1, HH);
    }

    // --- layer 0 (mma.sync): h1 splits = relu(xout @ Wl + bl + c*Wc + x*Wa) ---
    {
        dim3 grid(LM / 128, (n + 127) / 128);
        k_gemm_mma<1, 1, 1><<<grid, 256, SMEM_MMA>>>(n, c, x, Wc, Wa, bl);
    }
    // --- conv1 projection (mma.sync): g_hp1 = h1 @ W1 ---
    {
        dim3 grid(HH / 128, (n + 127) / 128);
        k_gemm_mma<0, 2, 2><<<grid, 256, SMEM_MMA>>>(n, nullptr, nullptr, nullptr, nullptr, nullptr);
    }
    // --- conv1 aggregation + bias + relu: g_h2 ---
    k_agg<HH, true, 2, 3><<<(n * 32 + 255) / 256, 256>>>(b1, nullptr, n);

    // --- conv3 projection (SIMT): g_hp3 = g_h2 @ W3 ---
    {
        dim3 grid(OUTC / 64, (n + 127) / 128);
        k_gemm<128, 64, 16, 8, 4, 3, 4><<<grid, 256>>>(nullptr, W3, nullptr, n, OUTC, HH);
    }
    // --- conv3 aggregation + bias: out ---
    k_agg<OUTC, false, 4, 0><<<(n * 32 + 255) / 256, 256>>>(b3, out, n);
}

// round 10
// speedup vs baseline: 1.5058x; 1.3481x over previous
#include <cuda_runtime.h>
#include <cuda_fp16.h>
#include <cstdint>

// Problem constants (fixed shapes for this problem instance)
#define NN   50000
#define EE   800000
#define LM   1024
#define HH   128
#define OUTC 64

// ---------------- scratch (static __device__, no allocation) ----------------
__device__ __half g_xh [(size_t)NN * LM];   // xout fp16 (single)
__device__ __half g_h1h[(size_t)NN * LM];   // h1 fp16 (single)
__device__ __half g_wth [(size_t)LM * LM];  // Wl^T hi   [1024,1024]
__device__ __half g_wtl [(size_t)LM * LM];  // Wl^T lo
__device__ __half g_w1th[(size_t)HH * LM];  // W1^T hi   [128,1024]
__device__ __half g_w1tl[(size_t)HH * LM];  // W1^T lo
__device__ float g_hp1[(size_t)NN * HH];    // h1 @ W1
__device__ float g_h2 [(size_t)NN * HH];    // conv1 output (relu'd)
__device__ float g_hp3[(size_t)NN * OUTC];  // h2 @ W3
__device__ float g_deg [NN];
__device__ float g_dis [NN];
__device__ int   g_cnt [NN];
__device__ int   g_rowptr[NN + 1];
__device__ int   g_bsum[64];
__device__ int   g_csr_src [EE];
__device__ float g_csr_coef[EE];
__device__ int   g_is64;

// ---------------- portable PTX helpers (sm_80+, compile for compute_103) ----
__device__ __forceinline__ uint32_t smem_to_u32(const void* p) {
    uint32_t a;
    asm("{ .reg .u64 t; cvta.to.shared.u64 t, %1; cvt.u32.u64 %0, t; }" : "=r"(a) : "l"(p));
    return a;
}
#define CP_ASYNC16(saddr, gaddr, sz) \
    asm volatile("cp.async.cg.shared.global [%0], [%1], 16, %2;" \
        :: "r"(saddr), "l"(gaddr), "r"(sz))
#define CP_COMMIT() asm volatile("cp.async.commit_group;" ::: "memory")
#define CP_WAIT(n)  asm volatile("cp.async.wait_group %0;" :: "n"(n) : "memory")
#define LDSM_X4(R, ADDR) \
    asm volatile("ldmatrix.sync.aligned.m8n8.x4.shared.b16 {%0,%1,%2,%3}, [%4];" \
        : "=r"((R)[0]), "=r"((R)[1]), "=r"((R)[2]), "=r"((R)[3]) : "r"(ADDR))

__device__ __forceinline__ void mma_fp16(float* d, const uint32_t* a,
                                         uint32_t b0, uint32_t b1) {
    asm volatile(
        "mma.sync.aligned.m16n8k16.row.col.f32.f16.f16.f32 "
        "{%0,%1,%2,%3}, {%4,%5,%6,%7}, {%8,%9}, {%0,%1,%2,%3};"
        : "+f"(d[0]), "+f"(d[1]), "+f"(d[2]), "+f"(d[3])
        : "r"(a[0]), "r"(a[1]), "r"(a[2]), "r"(a[3]), "r"(b0), "r"(b1));
}

// ---------------- buffer selectors (avoid host symbol lookups) ----------------
__device__ __forceinline__ float* sel_buf(int SEL, float* p) {
    switch (SEL) {
        case 2: return g_hp1;
        case 3: return g_h2;
        case 4: return g_hp3;
        default: return p;
    }
}
__device__ __forceinline__ const __half* sel_a(int SEL) {
    return (SEL == 1) ? g_xh : g_h1h;
}
__device__ __forceinline__ const __half* sel_b(int SEL, int lo) {
    if (SEL == 1) return lo ? g_wtl  : g_wth;
    else          return lo ? g_w1tl : g_w1th;
}

// edge index fetch honoring detected dtype
__device__ __forceinline__ int edge_at(const void* ei, long long idx) {
    if (g_is64) return (int)((const long long*)ei)[idx];
    return ((const int*)ei)[idx];
}

// ---------------- dtype detection ----------------
__global__ void k_detect(const unsigned int* __restrict__ w) {
    if (threadIdx.x == 0 && blockIdx.x == 0) {
        int is64 = 1;
        for (int i = 1; i < 64; i += 2)
            if (w[i] != 0u) { is64 = 0; break; }
        g_is64 = is64;
    }
}

// ---------------- graph preprocessing ----------------
__global__ void k_init(int n) {
    int i = blockIdx.x * blockDim.x + threadIdx.x;
    if (i < n) { g_deg[i] = 1.0f; g_cnt[i] = 0; }
}

__global__ void k_count(const void* __restrict__ ei, const float* __restrict__ ew, int e_) {
    int e = blockIdx.x * blockDim.x + threadIdx.x;
    if (e >= e_) return;
    int d = edge_at(ei, (long long)e_ + e);
    atomicAdd(&g_deg[d], ew[e]);
    atomicAdd(&g_cnt[d], 1);
}

// multi-block scan, phase A: per-block local exclusive scan + block totals
__global__ void k_scanA(int n) {
    __shared__ int wsum[32];
    int tid  = threadIdx.x;
    int warp = tid >> 5;
    int idx  = blockIdx.x * 1024 + tid;
    int v = (idx < n) ? g_cnt[idx] : 0;
    int inc = v;
    #pragma unroll
    for (int o = 1; o < 32; o <<= 1) {
        int nb = __shfl_up_sync(0xffffffffu, inc, o);
        if ((tid & 31) >= o) inc += nb;
    }
    if ((tid & 31) == 31) wsum[warp] = inc;
    __syncthreads();
    if (tid < 32) {
        int w = wsum[tid];
        #pragma unroll
        for (int o = 1; o < 32; o <<= 1) {
            int nb = __shfl_up_sync(0xffffffffu, w, o);
            if (tid >= o) w += nb;
        }
        wsum[tid] = w;
    }
    __syncthreads();
    int excl = inc - v + ((warp > 0) ? wsum[warp - 1] : 0);
    if (idx < n) {
        g_rowptr[idx] = excl;
        g_cnt[idx]    = 0;
        g_dis[idx]    = rsqrtf(g_deg[idx]);
    }
    if (tid == 0) g_bsum[blockIdx.x] = wsum[31];
}

// phase B: add block offsets (each block redundantly reduces prior block sums)
__global__ void k_scanB(int n, int e_) {
    __shared__ int s_off;
    int tid = threadIdx.x;
    if (tid < 32) {
        int acc = 0;
        for (int i = tid; i < (int)blockIdx.x; i += 32) acc += g_bsum[i];
        #pragma unroll
        for (int o = 16; o > 0; o >>= 1)
            acc += __shfl_down_sync(0xffffffffu, acc, o);
        if (tid == 0) s_off = acc;
    }
    __syncthreads();
    int idx = blockIdx.x * 1024 + tid;
    if (idx < n) g_rowptr[idx] += s_off;
    if (idx == n - 1) g_rowptr[n] = e_;
}

__global__ void k_fill(const void* __restrict__ ei, const float* __restrict__ ew, int e_) {
    int e = blockIdx.x * blockDim.x + threadIdx.x;
    if (e >= e_) return;
    int s = edge_at(ei, e);
    int d = edge_at(ei, (long long)e_ + e);
    int p = g_rowptr[d] + atomicAdd(&g_cnt[d], 1);
    g_csr_src[p]  = s;
    g_csr_coef[p] = g_dis[s] * ew[e] * g_dis[d];
}

// ---------------- fp16 conversion kernels ----------------
__global__ void k_cvt_x(const float* __restrict__ src, long long total) {
    long long i = (long long)blockIdx.x * blockDim.x + threadIdx.x;
    if (i >= total) return;
    g_xh[i] = __float2half(src[i]);
}
// W [K=1024, NO] row-major  ->  WT hi/lo [NO, 1024] fp16
template <int WSEL>
__global__ void k_split_wt(const float* __restrict__ W, int NO) {
    int idx = blockIdx.x * blockDim.x + threadIdx.x;
    if (idx >= LM * NO) return;
    int k = idx / NO, nn = idx % NO;
    float v = W[idx];
    __half h = __float2half(v);
    __half l = __float2half(v - __half2float(h));
    __half* th = (WSEL == 1) ? g_wth : g_w1th;
    __half* tl = (WSEL == 1) ? g_wtl : g_w1tl;
    th[(size_t)nn * LM + k] = h;
    tl[(size_t)nn * LM + k] = l;
}

// ---------------- mma.sync fp16 asymmetric-split GEMM ----------------
// D[M, NG] = A[M,1024] @ B^T, A fp16 single, B^T rows = Bh + Bl (2 products).
// Block 128x128, BK=32, 8 warps (warp tile 32x64), cp.async 3-stage pipeline.
// EPI=1: v = d + bl + c*Wc + x*Wa, relu, store fp16 -> g_h1h (stride LM)
// EPI=0: store fp32 -> g_hp1 (stride HH)
template <int EPI, int ASEL, int BSEL>
__global__ __launch_bounds__(256)
void k_gemm_mma(int M,
                const float* __restrict__ cvec, const float* __restrict__ xvec,
                const float* __restrict__ Wc,   const float* __restrict__ Wa,
                const float* __restrict__ bl) {
    constexpr int BK  = 32;
    constexpr int NIT = LM / BK;            // 32
    constexpr int STAGE = 24576;            // A 8K | Bh 8K | Bl 8K
    constexpr int NSTAGE = 3;

    extern __shared__ char smem[];
    const uint32_t sbase0 = smem_to_u32(smem);

    const int tid    = threadIdx.x;
    const int lane   = tid & 31;
    const int wid    = tid >> 5;
    const int warp_m = wid & 3;             // 4 warps in M (32 rows each)
    const int warp_n = wid >> 2;            // 2 warps in N (64 cols each)

    const int block_row = blockIdx.y * 128;
    const int block_col = blockIdx.x * 128;

    const __half* __restrict__ Ah = sel_a(ASEL);
    const __half* __restrict__ Bh = sel_b(BSEL, 0);
    const __half* __restrict__ Bl = sel_b(BSEL, 1);

    // per-thread load slots: idx -> (row = idx>>2, 16B chunk = idx&3)
    const int r0  = tid >> 2,            cb0 = tid & 3;
    const int r1  = (tid + 256) >> 2,    cb1 = tid & 3;
    const uint32_t so0 = (uint32_t)(r0 * 64 + ((cb0 ^ ((r0 >> 1) & 3)) * 16));
    const uint32_t so1 = (uint32_t)(r1 * 64 + ((cb1 ^ ((r1 >> 1) & 3)) * 16));

    auto issue_tile = [&](int stage, int k0) {
        uint32_t sb = sbase0 + stage * STAGE;
        {
            long long arow = block_row + r0;
            size_t ga = (size_t)arow * LM + k0 + cb0 * 8;
            uint32_t asz = (arow < M) ? 16u : 0u;
            CP_ASYNC16(sb + so0,         (const char*)(Ah + ga), asz);
            size_t gb = (size_t)(block_col + r0) * LM + k0 + cb0 * 8;
            CP_ASYNC16(sb + 8192  + so0, (const char*)(Bh + gb), 16u);
            CP_ASYNC16(sb + 16384 + so0, (const char*)(Bl + gb), 16u);
        }
        {
            long long arow = block_row + r1;
            size_t ga = (size_t)arow * LM + k0 + cb1 * 8;
            uint32_t asz = (arow < M) ? 16u : 0u;
            CP_ASYNC16(sb + so1,         (const char*)(Ah + ga), asz);
            size_t gb = (size_t)(block_col + r1) * LM + k0 + cb1 * 8;
            CP_ASYNC16(sb + 8192  + so1, (const char*)(Bh + gb), 16u);
            CP_ASYNC16(sb + 16384 + so1, (const char*)(Bl + gb), 16u);
        }
        CP_COMMIT();
    };

    float acc[2][8][4];
    #pragma unroll
    for (int i = 0; i < 2; i++)
        #pragma unroll
        for (int j = 0; j < 8; j++)
            #pragma unroll
            for (int q = 0; q < 4; q++) acc[i][j][q] = 0.0f;

    issue_tile(0, 0);
    issue_tile(1, BK);

    int stage = 0;
    for (int it = 0; it < NIT; it++) {
        if (it + 2 < NIT) {
            issue_tile((it + 2) % NSTAGE, (it + 2) * BK);
            CP_WAIT(2);
        } else {
            CP_WAIT(0);
        }
        __syncthreads();

        const uint32_t sb = sbase0 + stage * STAGE;
        #pragma unroll
        for (int ks = 0; ks < 2; ks++) {
            uint32_t aH[2][4];
            #pragma unroll
            for (int mt = 0; mt < 2; mt++) {
                int row = warp_m * 32 + mt * 16 + (lane & 15);
                int cb  = ks * 2 + (lane >> 4);
                uint32_t off = (uint32_t)(row * 64 + ((cb ^ ((row >> 1) & 3)) * 16));
                LDSM_X4(aH[mt], sb + off);
            }
            #pragma unroll
            for (int g = 0; g < 4; g++) {
                uint32_t bh[4], blr[4];
                int row = warp_n * 64 + g * 16 + (lane & 15);
                int cb  = ks * 2 + (lane >> 4);
                uint32_t off = (uint32_t)(row * 64 + ((cb ^ ((row >> 1) & 3)) * 16));
                LDSM_X4(bh,  sb + 8192  + off);
                LDSM_X4(blr, sb + 16384 + off);
                #pragma unroll
                for (int mt = 0; mt < 2; mt++) {
                    #pragma unroll
                    for (int sub = 0; sub < 2; sub++) {
                        int nt = g * 2 + sub;
                        mma_fp16(acc[mt][nt], aH[mt], bh[sub],  bh[sub + 2]);   // A*Bhi
                        mma_fp16(acc[mt][nt], aH[mt], blr[sub], blr[sub + 2]);  // A*Blo
                    }
                }
            }
        }
        __syncthreads();
        stage = (stage + 1 == NSTAGE) ? 0 : stage + 1;
    }

    // ---------------- epilogue ----------------
    #pragma unroll
    for (int nt = 0; nt < 8; nt++) {
        int col = block_col + warp_n * 64 + nt * 8 + (lane & 3) * 2;
        float bl0 = 0.f, bl1 = 0.f, wc0 = 0.f, wc1 = 0.f, wa0 = 0.f, wa1 = 0.f;
        if (EPI == 1) {
            bl0 = bl[col];  bl1 = bl[col + 1];
            wc0 = Wc[col];  wc1 = Wc[col + 1];
            wa0 = Wa[col];  wa1 = Wa[col + 1];
        }
        #pragma unroll
        for (int mt = 0; mt < 2; mt++) {
            int rbase = block_row + warp_m * 32 + mt * 16 + (lane >> 2);
            #pragma unroll
            for (int h = 0; h < 2; h++) {
                int row = rbase + h * 8;
                if (row >= M) continue;
                float v0 = acc[mt][nt][h * 2 + 0];
                float v1 = acc[mt][nt][h * 2 + 1];
                if (EPI == 1) {
                    float cv = cvec[row], xv = xvec[row];
                    v0 = fmaxf(v0 + bl0 + cv * wc0 + xv * wa0, 0.f);
                    v1 = fmaxf(v1 + bl1 + cv * wc1 + xv * wa1, 0.f);
                    __half2 hh;
                    hh.x = __float2half(v0);
                    hh.y = __float2half(v1);
                    *(__half2*)&g_h1h[(size_t)row * LM + col] = hh;
                } else {
                    float2 f2; f2.x = v0; f2.y = v1;
                    *(float2*)&g_hp1[(size_t)row * HH + col] = f2;
                }
            }
        }
    }
}

// ---------------- SIMT GEMM (small conv3 projection) ----------------
template <int BM, int BN, int BK, int TM, int TN, int ASEL, int DSEL>
__global__ __launch_bounds__((BM / TM) * (BN / TN))
void k_gemm(const float* __restrict__ Ap, const float* __restrict__ B,
            float* __restrict__ Cp, int M, int N, int K) {
    const float* __restrict__ A = sel_buf(ASEL, (float*)Ap);
    float* __restrict__ C = sel_buf(DSEL, Cp);

    constexpr int THREADS = (BM / TM) * (BN / TN);
    __shared__ float As[BK][BM];
    __shared__ float Bs[BK][BN];

    const int block_row = blockIdx.y * BM;
    const int block_col = blockIdx.x * BN;
    const int tid  = threadIdx.x;
    const int tcol = tid % (BN / TN);
    const int trow = tid / (BN / TN);

    float acc[TM][TN];
    #pragma unroll
    for (int i = 0; i < TM; i++)
        #pragma unroll
        for (int j = 0; j < TN; j++) acc[i][j] = 0.0f;

    for (int k0 = 0; k0 < K; k0 += BK) {
        #pragma unroll
        for (int i = tid; i < BM * BK / 4; i += THREADS) {
            int r  = i / (BK / 4);
            int c4 = i % (BK / 4);
            int grow = block_row + r;
            float4 v = (grow < M)
                ? *(const float4*)&A[(size_t)grow * K + k0 + c4 * 4]
                : make_float4(0.f, 0.f, 0.f, 0.f);
            As[c4 * 4 + 0][r] = v.x;
            As[c4 * 4 + 1][r] = v.y;
            As[c4 * 4 + 2][r] = v.z;
            As[c4 * 4 + 3][r] = v.w;
        }
        #pragma unroll
        for (int i = tid; i < BK * BN / 4; i += THREADS) {
            int r  = i / (BN / 4);
            int c4 = i % (BN / 4);
            *(float4*)&Bs[r][c4 * 4] =
                *(const float4*)&B[(size_t)(k0 + r) * N + block_col + c4 * 4];
        }
        __syncthreads();
        #pragma unroll
        for (int k = 0; k < BK; k++) {
            float a[TM], b[TN];
            #pragma unroll
            for (int i = 0; i < TM; i++) a[i] = As[k][trow * TM + i];
            #pragma unroll
            for (int j = 0; j < TN; j++) b[j] = Bs[k][tcol * TN + j];
            #pragma unroll
            for (int i = 0; i < TM; i++)
                #pragma unroll
                for (int j = 0; j < TN; j++)
                    acc[i][j] = fmaf(a[i], b[j], acc[i][j]);
        }
        __syncthreads();
    }
    #pragma unroll
    for (int i = 0; i < TM; i++) {
        int grow = block_row + trow * TM + i;
        if (grow >= M) continue;
        #pragma unroll
        for (int j = 0; j < TN; j++) {
            int gcol = block_col + tcol * TN + j;
            C[(size_t)grow * N + gcol] = acc[i][j];
        }
    }
}

// ---------------- GCN aggregation (CSR gather, warp per node) ----------------
template <int F, bool RELU, int HPSEL, int OSEL>
__global__ void k_agg(const float* __restrict__ bias, float* __restrict__ outp, int n) {
    const float* __restrict__ hp = sel_buf(HPSEL, nullptr);
    float* __restrict__ out = sel_buf(OSEL, outp);

    int warp = (blockIdx.x * blockDim.x + threadIdx.x) >> 5;
    int lane = threadIdx.x & 31;
    if (warp >= n) return;
    const int node = warp;
    constexpr int V = F / 32;
    float acc[V];

    float selfc = g_dis[node] * g_dis[node];
    const float* hrow = hp + (size_t)node * F + lane * V;
    #pragma unroll
    for (int j = 0; j < V; j++) acc[j] = selfc * hrow[j];

    int beg = g_rowptr[node];
    int end = g_rowptr[node + 1];
    for (int e = beg; e < end; e++) {
        int   s  = g_csr_src[e];
        float cf = g_csr_coef[e];
        const float* srow = hp + (size_t)s * F + lane * V;
        if (V == 4) {
            float4 v = *(const float4*)srow;
            acc[0] = fmaf(cf, v.x, acc[0]);
            acc[1] = fmaf(cf, v.y, acc[1]);
            acc[2] = fmaf(cf, v.z, acc[2]);
            acc[3] = fmaf(cf, v.w, acc[3]);
        } else {
            float2 v = *(const float2*)srow;
            acc[0] = fmaf(cf, v.x, acc[0]);
            acc[1] = fmaf(cf, v.y, acc[1]);
        }
    }
    #pragma unroll
    for (int j = 0; j < V; j++) {
        float v = acc[j] + bias[lane * V + j];
        if (RELU) v = fmaxf(v, 0.f);
        out[(size_t)node * F + lane * V + j] = v;
    }
}

// ---------------- launch ----------------
extern "C" void kernel_launch(void* const* d_in, const int* in_sizes, int n_in,
                              void* d_out, int out_size) {
    const float* x    = (const float*)d_in[0];
    const float* xout = (const float*)d_in[1];
    const float* c    = (const float*)d_in[2];
    const void*  ei   = d_in[3];
    const float* ew   = (const float*)d_in[4];
    const float* Wa   = (const float*)d_in[5];
    const float* Wc   = (const float*)d_in[6];
    const float* Wl   = (const float*)d_in[7];
    const float* bl   = (const float*)d_in[8];
    const float* W1   = (const float*)d_in[9];
    const float* b1   = (const float*)d_in[10];
    const float* W3   = (const float*)d_in[11];
    const float* b3   = (const float*)d_in[12];
    float* out = (float*)d_out;

    const int n = in_sizes[0];
    const int e = in_sizes[3] / 2;

    const int SMEM_MMA = 3 * 24576;   // 72 KB dynamic (3 stages)
    cudaFuncSetAttribute(k_gemm_mma<1, 1, 1>,
                         cudaFuncAttributeMaxDynamicSharedMemorySize, SMEM_MMA);
    cudaFuncSetAttribute(k_gemm_mma<0, 2, 2>,
                         cudaFuncAttributeMaxDynamicSharedMemorySize, SMEM_MMA);

    // --- dtype detection + graph preprocessing ---
    const int nblk = (n + 1023) / 1024;
    k_detect<<<1, 32>>>((const unsigned int*)ei);
    k_init  <<<(n + 255) / 256, 256>>>(n);
    k_count <<<(e + 255) / 256, 256>>>(ei, ew, e);
    k_scanA <<<nblk, 1024>>>(n);
    k_scanB <<<nblk, 1024>>>(n, e);
    k_fill  <<<(e + 255) / 256, 256>>>(ei, ew, e);

    // --- fp16 conversion: xout (single), Wl^T and W1^T (hi+lo) ---
    {
        long long tot = (long long)n * LM;
        k_cvt_x<<<(unsigned)((tot + 511) / 512), 512>>>(xout, tot);
        k_split_wt<1><<<(LM * LM + 255) / 256, 256>>>(Wl, LM);
        k_split_wt<2><<<(LM * HH + 255) / 256, 256>>>(W1, HH);
    }

    // --- layer 0 (mma.sync): h1 = relu(xout @ Wl + bl + c*Wc + x*Wa) -> fp16 ---
    {
        dim3 grid(LM / 128, (n + 127) / 128);
        k_gemm_mma<1, 1, 1><<<grid, 256, SMEM_MMA>>>(n, c, x, Wc, Wa, bl);
    }
    // --- conv1 projection (mma.sync): g_hp1 = h1 @ W1 ---
    {
        dim3 grid(HH / 128, (n + 127) / 128);
        k_gemm_mma<0, 2, 2><<<grid, 256, SMEM_MMA>>>(n, nullptr, nullptr, nullptr, nullptr, nullptr);
    }
    // --- conv1 aggregation + bias + relu: g_h2 ---
    k_agg<HH, true, 2, 3><<<(n * 32 + 255) / 256, 256>>>(b1, nullptr, n);

    // --- conv3 projection (SIMT): g_hp3 = g_h2 @ W3 ---
    {
        dim3 grid(OUTC / 64, (n + 127) / 128);
        k_gemm<128, 64, 16, 8, 4, 3, 4><<<grid, 256>>>(nullptr, W3, nullptr, n, OUTC, HH);
    }
    // --- conv3 aggregation + bias: out ---
    k_agg<OUTC, false, 4, 0><<<(n * 32 + 255) / 256, 256>>>(b3, out, n);
}

// round 11
// speedup vs baseline: 2.0385x; 1.3537x over previous
#include <cuda_runtime.h>
#include <cuda_fp16.h>
#include <cstdint>

// Problem constants (fixed shapes for this problem instance)
#define NN   50000
#define EE   800000
#define LM   1024
#define HH   128
#define OUTC 64

// ---------------- scratch (static __device__, no allocation) ----------------
__device__ __half g_xh [(size_t)NN * LM];   // xout fp16
__device__ __half g_h1h[(size_t)NN * LM];   // h1 fp16
__device__ __half g_wth [(size_t)LM * LM];  // Wl^T fp16  [1024,1024]
__device__ __half g_w1th[(size_t)HH * LM];  // W1^T fp16  [128,1024]
__device__ float g_hp1[(size_t)NN * HH];    // h1 @ W1
__device__ float g_h2 [(size_t)NN * HH];    // conv1 output (relu'd)
__device__ float g_hp3[(size_t)NN * OUTC];  // h2 @ W3
__device__ float g_deg [NN];
__device__ float g_dis [NN];
__device__ int   g_cnt [NN];
__device__ int   g_rowptr[NN + 1];
__device__ int   g_bsum[64];
__device__ int   g_csr_src [EE];
__device__ float g_csr_coef[EE];
__device__ int   g_is64;

// ---------------- portable PTX helpers (sm_80+, compile for compute_103) ----
__device__ __forceinline__ uint32_t smem_to_u32(const void* p) {
    uint32_t a;
    asm("{ .reg .u64 t; cvta.to.shared.u64 t, %1; cvt.u32.u64 %0, t; }" : "=r"(a) : "l"(p));
    return a;
}
#define CP_ASYNC16(saddr, gaddr, sz) \
    asm volatile("cp.async.cg.shared.global [%0], [%1], 16, %2;" \
        :: "r"(saddr), "l"(gaddr), "r"(sz))
#define CP_COMMIT() asm volatile("cp.async.commit_group;" ::: "memory")
#define CP_WAIT(n)  asm volatile("cp.async.wait_group %0;" :: "n"(n) : "memory")
#define LDSM_X4(R, ADDR) \
    asm volatile("ldmatrix.sync.aligned.m8n8.x4.shared.b16 {%0,%1,%2,%3}, [%4];" \
        : "=r"((R)[0]), "=r"((R)[1]), "=r"((R)[2]), "=r"((R)[3]) : "r"(ADDR))

__device__ __forceinline__ void mma_fp16(float* d, const uint32_t* a,
                                         uint32_t b0, uint32_t b1) {
    asm volatile(
        "mma.sync.aligned.m16n8k16.row.col.f32.f16.f16.f32 "
        "{%0,%1,%2,%3}, {%4,%5,%6,%7}, {%8,%9}, {%0,%1,%2,%3};"
        : "+f"(d[0]), "+f"(d[1]), "+f"(d[2]), "+f"(d[3])
        : "r"(a[0]), "r"(a[1]), "r"(a[2]), "r"(a[3]), "r"(b0), "r"(b1));
}

// ---------------- buffer selectors (avoid host symbol lookups) ----------------
__device__ __forceinline__ float* sel_buf(int SEL, float* p) {
    switch (SEL) {
        case 2: return g_hp1;
        case 3: return g_h2;
        case 4: return g_hp3;
        default: return p;
    }
}
__device__ __forceinline__ const __half* sel_a(int SEL) {
    return (SEL == 1) ? g_xh : g_h1h;
}
__device__ __forceinline__ const __half* sel_b(int SEL) {
    return (SEL == 1) ? g_wth : g_w1th;
}

// edge index fetch honoring detected dtype
__device__ __forceinline__ int edge_at(const void* ei, long long idx) {
    if (g_is64) return (int)((const long long*)ei)[idx];
    return ((const int*)ei)[idx];
}

// ---------------- dtype detection ----------------
__global__ void k_detect(const unsigned int* __restrict__ w) {
    if (threadIdx.x == 0 && blockIdx.x == 0) {
        int is64 = 1;
        for (int i = 1; i < 64; i += 2)
            if (w[i] != 0u) { is64 = 0; break; }
        g_is64 = is64;
    }
}

// ---------------- graph preprocessing ----------------
__global__ void k_init(int n) {
    int i = blockIdx.x * blockDim.x + threadIdx.x;
    if (i < n) { g_deg[i] = 1.0f; g_cnt[i] = 0; }
}

__global__ void k_count(const void* __restrict__ ei, const float* __restrict__ ew, int e_) {
    int e = blockIdx.x * blockDim.x + threadIdx.x;
    if (e >= e_) return;
    int d = edge_at(ei, (long long)e_ + e);
    atomicAdd(&g_deg[d], ew[e]);
    atomicAdd(&g_cnt[d], 1);
}

// multi-block scan, phase A: per-block local exclusive scan + block totals
__global__ void k_scanA(int n) {
    __shared__ int wsum[32];
    int tid  = threadIdx.x;
    int warp = tid >> 5;
    int idx  = blockIdx.x * 1024 + tid;
    int v = (idx < n) ? g_cnt[idx] : 0;
    int inc = v;
    #pragma unroll
    for (int o = 1; o < 32; o <<= 1) {
        int nb = __shfl_up_sync(0xffffffffu, inc, o);
        if ((tid & 31) >= o) inc += nb;
    }
    if ((tid & 31) == 31) wsum[warp] = inc;
    __syncthreads();
    if (tid < 32) {
        int w = wsum[tid];
        #pragma unroll
        for (int o = 1; o < 32; o <<= 1) {
            int nb = __shfl_up_sync(0xffffffffu, w, o);
            if (tid >= o) w += nb;
        }
        wsum[tid] = w;
    }
    __syncthreads();
    int excl = inc - v + ((warp > 0) ? wsum[warp - 1] : 0);
    if (idx < n) {
        g_rowptr[idx] = excl;
        g_cnt[idx]    = 0;
        g_dis[idx]    = rsqrtf(g_deg[idx]);
    }
    if (tid == 0) g_bsum[blockIdx.x] = wsum[31];
}

// phase B: add block offsets (each block redundantly reduces prior block sums)
__global__ void k_scanB(int n, int e_) {
    __shared__ int s_off;
    int tid = threadIdx.x;
    if (tid < 32) {
        int acc = 0;
        for (int i = tid; i < (int)blockIdx.x; i += 32) acc += g_bsum[i];
        #pragma unroll
        for (int o = 16; o > 0; o >>= 1)
            acc += __shfl_down_sync(0xffffffffu, acc, o);
        if (tid == 0) s_off = acc;
    }
    __syncthreads();
    int idx = blockIdx.x * 1024 + tid;
    if (idx < n) g_rowptr[idx] += s_off;
    if (idx == n - 1) g_rowptr[n] = e_;
}

__global__ void k_fill(const void* __restrict__ ei, const float* __restrict__ ew, int e_) {
    int e = blockIdx.x * blockDim.x + threadIdx.x;
    if (e >= e_) return;
    int s = edge_at(ei, e);
    int d = edge_at(ei, (long long)e_ + e);
    int p = g_rowptr[d] + atomicAdd(&g_cnt[d], 1);
    g_csr_src[p]  = s;
    g_csr_coef[p] = g_dis[s] * ew[e] * g_dis[d];
}

// ---------------- fp16 conversion kernels ----------------
__global__ void k_cvt_x(const float* __restrict__ src, long long total) {
    long long i = (long long)blockIdx.x * blockDim.x + threadIdx.x;
    if (i >= total) return;
    g_xh[i] = __float2half(src[i]);
}
// W [K=1024, NO] row-major  ->  WT [NO, 1024] fp16
template <int WSEL>
__global__ void k_cvt_wt(const float* __restrict__ W, int NO) {
    int idx = blockIdx.x * blockDim.x + threadIdx.x;
    if (idx >= LM * NO) return;
    int k = idx / NO, nn = idx % NO;
    __half* th = (WSEL == 1) ? g_wth : g_w1th;
    th[(size_t)nn * LM + k] = __float2half(W[idx]);
}

// ---------------- mma.sync fp16 GEMM ----------------
// D[M, NG] = A[M,1024] @ B^T, fp16 x fp16 -> fp32 accum.
// Block 128x128, BK=32, 8 warps (warp tile 32x64), cp.async 3-stage pipeline.
// EPI=1: v = d + bl + c*Wc + x*Wa, relu, store fp16 -> g_h1h (stride LM)
// EPI=0: store fp32 -> g_hp1 (stride HH)
template <int EPI, int ASEL, int BSEL>
__global__ __launch_bounds__(256)
void k_gemm_mma(int M,
                const float* __restrict__ cvec, const float* __restrict__ xvec,
                const float* __restrict__ Wc,   const float* __restrict__ Wa,
                const float* __restrict__ bl) {
    constexpr int BK  = 32;
    constexpr int NIT = LM / BK;            // 32
    constexpr int STAGE = 16384;            // A 8K | B 8K
    constexpr int NSTAGE = 3;

    extern __shared__ char smem[];
    const uint32_t sbase0 = smem_to_u32(smem);

    const int tid    = threadIdx.x;
    const int lane   = tid & 31;
    const int wid    = tid >> 5;
    const int warp_m = wid & 3;             // 4 warps in M (32 rows each)
    const int warp_n = wid >> 2;            // 2 warps in N (64 cols each)

    const int block_row = blockIdx.y * 128;
    const int block_col = blockIdx.x * 128;

    const __half* __restrict__ Ah = sel_a(ASEL);
    const __half* __restrict__ Bh = sel_b(BSEL);

    // per-thread load slots: idx -> (row = idx>>2, 16B chunk = idx&3)
    const int r0  = tid >> 2,            cb0 = tid & 3;
    const int r1  = (tid + 256) >> 2,    cb1 = tid & 3;
    const uint32_t so0 = (uint32_t)(r0 * 64 + ((cb0 ^ ((r0 >> 1) & 3)) * 16));
    const uint32_t so1 = (uint32_t)(r1 * 64 + ((cb1 ^ ((r1 >> 1) & 3)) * 16));

    auto issue_tile = [&](int stage, int k0) {
        uint32_t sb = sbase0 + stage * STAGE;
        {
            long long arow = block_row + r0;
            size_t ga = (size_t)arow * LM + k0 + cb0 * 8;
            uint32_t asz = (arow < M) ? 16u : 0u;
            CP_ASYNC16(sb + so0,        (const char*)(Ah + ga), asz);
            size_t gb = (size_t)(block_col + r0) * LM + k0 + cb0 * 8;
            CP_ASYNC16(sb + 8192 + so0, (const char*)(Bh + gb), 16u);
        }
        {
            long long arow = block_row + r1;
            size_t ga = (size_t)arow * LM + k0 + cb1 * 8;
            uint32_t asz = (arow < M) ? 16u : 0u;
            CP_ASYNC16(sb + so1,        (const char*)(Ah + ga), asz);
            size_t gb = (size_t)(block_col + r1) * LM + k0 + cb1 * 8;
            CP_ASYNC16(sb + 8192 + so1, (const char*)(Bh + gb), 16u);
        }
        CP_COMMIT();
    };

    float acc[2][8][4];
    #pragma unroll
    for (int i = 0; i < 2; i++)
        #pragma unroll
        for (int j = 0; j < 8; j++)
            #pragma unroll
            for (int q = 0; q < 4; q++) acc[i][j][q] = 0.0f;

    issue_tile(0, 0);
    issue_tile(1, BK);

    int stage = 0;
    for (int it = 0; it < NIT; it++) {
        if (it + 2 < NIT) {
            issue_tile((it + 2) % NSTAGE, (it + 2) * BK);
            CP_WAIT(2);
        } else {
            CP_WAIT(0);
        }
        __syncthreads();

        const uint32_t sb = sbase0 + stage * STAGE;
        #pragma unroll
        for (int ks = 0; ks < 2; ks++) {
            uint32_t aH[2][4];
            #pragma unroll
            for (int mt = 0; mt < 2; mt++) {
                int row = warp_m * 32 + mt * 16 + (lane & 15);
                int cb  = ks * 2 + (lane >> 4);
                uint32_t off = (uint32_t)(row * 64 + ((cb ^ ((row >> 1) & 3)) * 16));
                LDSM_X4(aH[mt], sb + off);
            }
            #pragma unroll
            for (int g = 0; g < 4; g++) {
                uint32_t bh[4];
                int row = warp_n * 64 + g * 16 + (lane & 15);
                int cb  = ks * 2 + (lane >> 4);
                uint32_t off = (uint32_t)(row * 64 + ((cb ^ ((row >> 1) & 3)) * 16));
                LDSM_X4(bh, sb + 8192 + off);
                #pragma unroll
                for (int mt = 0; mt < 2; mt++) {
                    #pragma unroll
                    for (int sub = 0; sub < 2; sub++) {
                        int nt = g * 2 + sub;
                        mma_fp16(acc[mt][nt], aH[mt], bh[sub], bh[sub + 2]);
                    }
                }
            }
        }
        __syncthreads();
        stage = (stage + 1 == NSTAGE) ? 0 : stage + 1;
    }

    // ---------------- epilogue ----------------
    #pragma unroll
    for (int nt = 0; nt < 8; nt++) {
        int col = block_col + warp_n * 64 + nt * 8 + (lane & 3) * 2;
        float bl0 = 0.f, bl1 = 0.f, wc0 = 0.f, wc1 = 0.f, wa0 = 0.f, wa1 = 0.f;
        if (EPI == 1) {
            bl0 = bl[col];  bl1 = bl[col + 1];
            wc0 = Wc[col];  wc1 = Wc[col + 1];
            wa0 = Wa[col];  wa1 = Wa[col + 1];
        }
        #pragma unroll
        for (int mt = 0; mt < 2; mt++) {
            int rbase = block_row + warp_m * 32 + mt * 16 + (lane >> 2);
            #pragma unroll
            for (int h = 0; h < 2; h++) {
                int row = rbase + h * 8;
                if (row >= M) continue;
                float v0 = acc[mt][nt][h * 2 + 0];
                float v1 = acc[mt][nt][h * 2 + 1];
                if (EPI == 1) {
                    float cv = cvec[row], xv = xvec[row];
                    v0 = fmaxf(v0 + bl0 + cv * wc0 + xv * wa0, 0.f);
                    v1 = fmaxf(v1 + bl1 + cv * wc1 + xv * wa1, 0.f);
                    __half2 hh;
                    hh.x = __float2half(v0);
                    hh.y = __float2half(v1);
                    *(__half2*)&g_h1h[(size_t)row * LM + col] = hh;
                } else {
                    float2 f2; f2.x = v0; f2.y = v1;
                    *(float2*)&g_hp1[(size_t)row * HH + col] = f2;
                }
            }
        }
    }
}

// ---------------- SIMT GEMM (small conv3 projection) ----------------
template <int BM, int BN, int BK, int TM, int TN, int ASEL, int DSEL>
__global__ __launch_bounds__((BM / TM) * (BN / TN))
void k_gemm(const float* __restrict__ Ap, const float* __restrict__ B,
            float* __restrict__ Cp, int M, int N, int K) {
    const float* __restrict__ A = sel_buf(ASEL, (float*)Ap);
    float* __restrict__ C = sel_buf(DSEL, Cp);

    constexpr int THREADS = (BM / TM) * (BN / TN);
    __shared__ float As[BK][BM];
    __shared__ float Bs[BK][BN];

    const int block_row = blockIdx.y * BM;
    const int block_col = blockIdx.x * BN;
    const int tid  = threadIdx.x;
    const int tcol = tid % (BN / TN);
    const int trow = tid / (BN / TN);

    float acc[TM][TN];
    #pragma unroll
    for (int i = 0; i < TM; i++)
        #pragma unroll
        for (int j = 0; j < TN; j++) acc[i][j] = 0.0f;

    for (int k0 = 0; k0 < K; k0 += BK) {
        #pragma unroll
        for (int i = tid; i < BM * BK / 4; i += THREADS) {
            int r  = i / (BK / 4);
            int c4 = i % (BK / 4);
            int grow = block_row + r;
            float4 v = (grow < M)
                ? *(const float4*)&A[(size_t)grow * K + k0 + c4 * 4]
                : make_float4(0.f, 0.f, 0.f, 0.f);
            As[c4 * 4 + 0][r] = v.x;
            As[c4 * 4 + 1][r] = v.y;
            As[c4 * 4 + 2][r] = v.z;
            As[c4 * 4 + 3][r] = v.w;
        }
        #pragma unroll
        for (int i = tid; i < BK * BN / 4; i += THREADS) {
            int r  = i / (BN / 4);
            int c4 = i % (BN / 4);
            *(float4*)&Bs[r][c4 * 4] =
                *(const float4*)&B[(size_t)(k0 + r) * N + block_col + c4 * 4];
        }
        __syncthreads();
        #pragma unroll
        for (int k = 0; k < BK; k++) {
            float a[TM], b[TN];
            #pragma unroll
            for (int i = 0; i < TM; i++) a[i] = As[k][trow * TM + i];
            #pragma unroll
            for (int j = 0; j < TN; j++) b[j] = Bs[k][tcol * TN + j];
            #pragma unroll
            for (int i = 0; i < TM; i++)
                #pragma unroll
                for (int j = 0; j < TN; j++)
                    acc[i][j] = fmaf(a[i], b[j], acc[i][j]);
        }
        __syncthreads();
    }
    #pragma unroll
    for (int i = 0; i < TM; i++) {
        int grow = block_row + trow * TM + i;
        if (grow >= M) continue;
        #pragma unroll
        for (int j = 0; j < TN; j++) {
            int gcol = block_col + tcol * TN + j;
            C[(size_t)grow * N + gcol] = acc[i][j];
        }
    }
}

// ---------------- GCN aggregation (CSR gather, warp per node) ----------------
template <int F, bool RELU, int HPSEL, int OSEL>
__global__ void k_agg(const float* __restrict__ bias, float* __restrict__ outp, int n) {
    const float* __restrict__ hp = sel_buf(HPSEL, nullptr);
    float* __restrict__ out = sel_buf(OSEL, outp);

    int warp = (blockIdx.x * blockDim.x + threadIdx.x) >> 5;
    int lane = threadIdx.x & 31;
    if (warp >= n) return;
    const int node = warp;
    constexpr int V = F / 32;
    float acc[V];

    float selfc = g_dis[node] * g_dis[node];
    const float* hrow = hp + (size_t)node * F + lane * V;
    #pragma unroll
    for (int j = 0; j < V; j++) acc[j] = selfc * hrow[j];

    int beg = g_rowptr[node];
    int end = g_rowptr[node + 1];
    for (int e = beg; e < end; e++) {
        int   s  = g_csr_src[e];
        float cf = g_csr_coef[e];
        const float* srow = hp + (size_t)s * F + lane * V;
        if (V == 4) {
            float4 v = *(const float4*)srow;
            acc[0] = fmaf(cf, v.x, acc[0]);
            acc[1] = fmaf(cf, v.y, acc[1]);
            acc[2] = fmaf(cf, v.z, acc[2]);
            acc[3] = fmaf(cf, v.w, acc[3]);
        } else {
            float2 v = *(const float2*)srow;
            acc[0] = fmaf(cf, v.x, acc[0]);
            acc[1] = fmaf(cf, v.y, acc[1]);
        }
    }
    #pragma unroll
    for (int j = 0; j < V; j++) {
        float v = acc[j] + bias[lane * V + j];
        if (RELU) v = fmaxf(v, 0.f);
        out[(size_t)node * F + lane * V + j] = v;
    }
}

// ---------------- launch ----------------
extern "C" void kernel_launch(void* const* d_in, const int* in_sizes, int n_in,
                              void* d_out, int out_size) {
    const float* x    = (const float*)d_in[0];
    const float* xout = (const float*)d_in[1];
    const float* c    = (const float*)d_in[2];
    const void*  ei   = d_in[3];
    const float* ew   = (const float*)d_in[4];
    const float* Wa   = (const float*)d_in[5];
    const float* Wc   = (const float*)d_in[6];
    const float* Wl   = (const float*)d_in[7];
    const float* bl   = (const float*)d_in[8];
    const float* W1   = (const float*)d_in[9];
    const float* b1   = (const float*)d_in[10];
    const float* W3   = (const float*)d_in[11];
    const float* b3   = (const float*)d_in[12];
    float* out = (float*)d_out;

    const int n = in_sizes[0];
    const int e = in_sizes[3] / 2;

    const int SMEM_MMA = 3 * 16384;   // 48 KB dynamic (3 stages)
    cudaFuncSetAttribute(k_gemm_mma<1, 1, 1>,
                         cudaFuncAttributeMaxDynamicSharedMemorySize, SMEM_MMA);
    cudaFuncSetAttribute(k_gemm_mma<0, 2, 2>,
                         cudaFuncAttributeMaxDynamicSharedMemorySize, SMEM_MMA);

    // --- dtype detection + graph preprocessing ---
    const int nblk = (n + 1023) / 1024;
    k_detect<<<1, 32>>>((const unsigned int*)ei);
    k_init  <<<(n + 255) / 256, 256>>>(n);
    k_count <<<(e + 255) / 256, 256>>>(ei, ew, e);
    k_scanA <<<nblk, 1024>>>(n);
    k_scanB <<<nblk, 1024>>>(n, e);
    k_fill  <<<(e + 255) / 256, 256>>>(ei, ew, e);

    // --- fp16 conversion: xout, Wl^T, W1^T ---
    {
        long long tot = (long long)n * LM;
        k_cvt_x<<<(unsigned)((tot + 511) / 512), 512>>>(xout, tot);
        k_cvt_wt<1><<<(LM * LM + 255) / 256, 256>>>(Wl, LM);
        k_cvt_wt<2><<<(LM * HH + 255) / 256, 256>>>(W1, HH);
    }

    // --- layer 0 (mma.sync): h1 = relu(xout @ Wl + bl + c*Wc + x*Wa) -> fp16 ---
    {
        dim3 grid(LM / 128, (n + 127) / 128);
        k_gemm_mma<1, 1, 1><<<grid, 256, SMEM_MMA>>>(n, c, x, Wc, Wa, bl);
    }
    // --- conv1 projection (mma.sync): g_hp1 = h1 @ W1 ---
    {
        dim3 grid(HH / 128, (n + 127) / 128);
        k_gemm_mma<0, 2, 2><<<grid, 256, SMEM_MMA>>>(n, nullptr, nullptr, nullptr, nullptr, nullptr);
    }
    // --- conv1 aggregation + bias + relu: g_h2 ---
    k_agg<HH, true, 2, 3><<<(n * 32 + 255) / 256, 256>>>(b1, nullptr, n);

    // --- conv3 projection (SIMT): g_hp3 = g_h2 @ W3 ---
    {
        dim3 grid(OUTC / 64, (n + 127) / 128);
        k_gemm<128, 64, 16, 8, 4, 3, 4><<<grid, 256>>>(nullptr, W3, nullptr, n, OUTC, HH);
    }
    // --- conv3 aggregation + bias: out ---
    k_agg<OUTC, false, 4, 0><<<(n * 32 + 255) / 256, 256>>>(b3, out, n);
}

// round 12
// speedup vs baseline: 2.1133x; 1.0367x over previous
#include <cuda_runtime.h>
#include <cuda_fp16.h>
#include <cstdint>

// Problem constants (fixed shapes for this problem instance)
#define NN   50000
#define EE   800000
#define LM   1024
#define HH   128
#define OUTC 64

// ---------------- scratch (static __device__, no allocation) ----------------
__device__ __half g_xh [(size_t)NN * LM];   // xout fp16
__device__ __half g_h1h[(size_t)NN * LM];   // h1 fp16
__device__ __half g_wth [(size_t)LM * LM];  // Wl^T fp16  [1024,1024]
__device__ __half g_w1th[(size_t)HH * LM];  // W1^T fp16  [128,1024]
__device__ __half g_w3t [(size_t)OUTC * HH];// W3^T fp16  [64,128]
__device__ __half g_hp1h[(size_t)NN * HH];  // h1 @ W1 (fp16)
__device__ __half g_h2h [(size_t)NN * HH];  // conv1 output relu'd (fp16)
__device__ float  g_hp3[(size_t)NN * OUTC]; // h2 @ W3 (fp32)
__device__ float g_deg [NN];
__device__ float g_dis [NN];
__device__ int   g_cnt [NN];
__device__ int   g_rowptr[NN + 1];
__device__ int   g_bsum[64];
__device__ int   g_csr_src [EE];
__device__ float g_csr_coef[EE];
__device__ int   g_is64;

// ---------------- portable PTX helpers (sm_80+, compile for compute_103) ----
__device__ __forceinline__ uint32_t smem_to_u32(const void* p) {
    uint32_t a;
    asm("{ .reg .u64 t; cvta.to.shared.u64 t, %1; cvt.u32.u64 %0, t; }" : "=r"(a) : "l"(p));
    return a;
}
#define CP_ASYNC16(saddr, gaddr, sz) \
    asm volatile("cp.async.cg.shared.global [%0], [%1], 16, %2;" \
        :: "r"(saddr), "l"(gaddr), "r"(sz))
#define CP_COMMIT() asm volatile("cp.async.commit_group;" ::: "memory")
#define CP_WAIT(n)  asm volatile("cp.async.wait_group %0;" :: "n"(n) : "memory")
#define LDSM_X4(R, ADDR) \
    asm volatile("ldmatrix.sync.aligned.m8n8.x4.shared.b16 {%0,%1,%2,%3}, [%4];" \
        : "=r"((R)[0]), "=r"((R)[1]), "=r"((R)[2]), "=r"((R)[3]) : "r"(ADDR))

__device__ __forceinline__ void mma_fp16(float* d, const uint32_t* a,
                                         uint32_t b0, uint32_t b1) {
    asm volatile(
        "mma.sync.aligned.m16n8k16.row.col.f32.f16.f16.f32 "
        "{%0,%1,%2,%3}, {%4,%5,%6,%7}, {%8,%9}, {%0,%1,%2,%3};"
        : "+f"(d[0]), "+f"(d[1]), "+f"(d[2]), "+f"(d[3])
        : "r"(a[0]), "r"(a[1]), "r"(a[2]), "r"(a[3]), "r"(b0), "r"(b1));
}

// ---------------- buffer selectors (avoid host symbol lookups) ----------------
__device__ __forceinline__ const __half* sel_a(int SEL) {
    if (SEL == 1) return g_xh;
    if (SEL == 2) return g_h1h;
    return g_h2h;
}
__device__ __forceinline__ const __half* sel_b(int SEL) {
    if (SEL == 1) return g_wth;
    if (SEL == 2) return g_w1th;
    return g_w3t;
}

// edge index fetch honoring detected dtype
__device__ __forceinline__ int edge_at(const void* ei, long long idx) {
    if (g_is64) return (int)((const long long*)ei)[idx];
    return ((const int*)ei)[idx];
}

// ---------------- fused dtype detection + init ----------------
__global__ void k_prep(const unsigned int* __restrict__ w, int n) {
    int i = blockIdx.x * blockDim.x + threadIdx.x;
    if (i == 0) {
        int is64 = 1;
        for (int j = 1; j < 64; j += 2)
            if (w[j] != 0u) { is64 = 0; break; }
        g_is64 = is64;
    }
    if (i < n) { g_deg[i] = 1.0f; g_cnt[i] = 0; }
}

__global__ void k_count(const void* __restrict__ ei, const float* __restrict__ ew, int e_) {
    int e = blockIdx.x * blockDim.x + threadIdx.x;
    if (e >= e_) return;
    int d = edge_at(ei, (long long)e_ + e);
    atomicAdd(&g_deg[d], ew[e]);
    atomicAdd(&g_cnt[d], 1);
}

// multi-block scan, phase A: per-block local exclusive scan + block totals
__global__ void k_scanA(int n) {
    __shared__ int wsum[32];
    int tid  = threadIdx.x;
    int warp = tid >> 5;
    int idx  = blockIdx.x * 1024 + tid;
    int v = (idx < n) ? g_cnt[idx] : 0;
    int inc = v;
    #pragma unroll
    for (int o = 1; o < 32; o <<= 1) {
        int nb = __shfl_up_sync(0xffffffffu, inc, o);
        if ((tid & 31) >= o) inc += nb;
    }
    if ((tid & 31) == 31) wsum[warp] = inc;
    __syncthreads();
    if (tid < 32) {
        int w = wsum[tid];
        #pragma unroll
        for (int o = 1; o < 32; o <<= 1) {
            int nb = __shfl_up_sync(0xffffffffu, w, o);
            if (tid >= o) w += nb;
        }
        wsum[tid] = w;
    }
    __syncthreads();
    int excl = inc - v + ((warp > 0) ? wsum[warp - 1] : 0);
    if (idx < n) {
        g_rowptr[idx] = excl;
        g_cnt[idx]    = 0;
        g_dis[idx]    = rsqrtf(g_deg[idx]);
    }
    if (tid == 0) g_bsum[blockIdx.x] = wsum[31];
}

// phase B: add block offsets
__global__ void k_scanB(int n, int e_) {
    __shared__ int s_off;
    int tid = threadIdx.x;
    if (tid < 32) {
        int acc = 0;
        for (int i = tid; i < (int)blockIdx.x; i += 32) acc += g_bsum[i];
        #pragma unroll
        for (int o = 16; o > 0; o >>= 1)
            acc += __shfl_down_sync(0xffffffffu, acc, o);
        if (tid == 0) s_off = acc;
    }
    __syncthreads();
    int idx = blockIdx.x * 1024 + tid;
    if (idx < n) g_rowptr[idx] += s_off;
    if (idx == n - 1) g_rowptr[n] = e_;
}

__global__ void k_fill(const void* __restrict__ ei, const float* __restrict__ ew, int e_) {
    int e = blockIdx.x * blockDim.x + threadIdx.x;
    if (e >= e_) return;
    int s = edge_at(ei, e);
    int d = edge_at(ei, (long long)e_ + e);
    int p = g_rowptr[d] + atomicAdd(&g_cnt[d], 1);
    g_csr_src[p]  = s;
    g_csr_coef[p] = g_dis[s] * ew[e] * g_dis[d];
}

// ---------------- fp16 conversion kernels ----------------
__global__ void k_cvt_x(const float* __restrict__ src, long long total) {
    long long i = (long long)blockIdx.x * blockDim.x + threadIdx.x;
    if (i >= total) return;
    g_xh[i] = __float2half(src[i]);
}
// W [K rows, NO cols] row-major -> WT [NO, K] fp16
template <int WSEL>
__global__ void k_cvt_wt(const float* __restrict__ W, int K, int NO) {
    int idx = blockIdx.x * blockDim.x + threadIdx.x;
    if (idx >= K * NO) return;
    int k = idx / NO, nn = idx % NO;
    __half* th = (WSEL == 1) ? g_wth : ((WSEL == 2) ? g_w1th : g_w3t);
    th[(size_t)nn * K + k] = __float2half(W[idx]);
}

// ---------------- mma.sync fp16 GEMM (generalized) ----------------
// D[M, *] = A[M,KDIM] @ B^T, fp16 x fp16 -> fp32 accum.
// Block 128xBN, BK=32, warp tile 32x64, cp.async 3-stage pipeline.
// EPI=1: layer0 epilogue (bias+rank1+relu), fp16 -> g_h1h (stride LM)
// EPI=2: fp16 -> g_hp1h (stride HH)
// EPI=3: fp32 -> g_hp3  (stride OUTC)
template <int EPI, int ASEL, int BSEL, int KDIM, int BN, int THREADS>
__global__ __launch_bounds__(THREADS)
void k_gemm_mma(int M,
                const float* __restrict__ cvec, const float* __restrict__ xvec,
                const float* __restrict__ Wc,   const float* __restrict__ Wa,
                const float* __restrict__ bl) {
    constexpr int BK  = 32;
    constexpr int NIT = KDIM / BK;
    constexpr int ASZ = 8192;               // 128 rows x 32 fp16
    constexpr int BSZ = BN * BK * 2;
    constexpr int STAGE = ASZ + BSZ;
    constexpr int NSTAGE = 3;

    extern __shared__ char smem[];
    const uint32_t sbase0 = smem_to_u32(smem);

    const int tid    = threadIdx.x;
    const int lane   = tid & 31;
    const int wid    = tid >> 5;
    const int warp_m = wid & 3;
    const int warp_n = wid >> 2;

    const int block_row = blockIdx.y * 128;
    const int block_col = blockIdx.x * BN;

    const __half* __restrict__ Ah = sel_a(ASEL);
    const __half* __restrict__ Bh = sel_b(BSEL);

    auto issue_tile = [&](int stage, int k0) {
        uint32_t sb = sbase0 + stage * STAGE;
        #pragma unroll
        for (int i = tid; i < 512; i += THREADS) {
            int r = i >> 2, cb = i & 3;
            uint32_t so = (uint32_t)(r * 64 + ((cb ^ ((r >> 1) & 3)) * 16));
            long long arow = block_row + r;
            size_t ga = (size_t)arow * KDIM + k0 + cb * 8;
            uint32_t asz = (arow < M) ? 16u : 0u;
            CP_ASYNC16(sb + so, (const char*)(Ah + ga), asz);
        }
        #pragma unroll
        for (int i = tid; i < BN * 4; i += THREADS) {
            int r = i >> 2, cb = i & 3;
            uint32_t so = (uint32_t)(r * 64 + ((cb ^ ((r >> 1) & 3)) * 16));
            size_t gb = (size_t)(block_col + r) * KDIM + k0 + cb * 8;
            CP_ASYNC16(sb + ASZ + so, (const char*)(Bh + gb), 16u);
        }
        CP_COMMIT();
    };

    float acc[2][8][4];
    #pragma unroll
    for (int i = 0; i < 2; i++)
        #pragma unroll
        for (int j = 0; j < 8; j++)
            #pragma unroll
            for (int q = 0; q < 4; q++) acc[i][j][q] = 0.0f;

    issue_tile(0, 0);
    issue_tile(1, BK);

    int stage = 0;
    for (int it = 0; it < NIT; it++) {
        if (it + 2 < NIT) {
            issue_tile((it + 2) % NSTAGE, (it + 2) * BK);
            CP_WAIT(2);
        } else {
            CP_WAIT(0);
        }
        __syncthreads();

        const uint32_t sb = sbase0 + stage * STAGE;
        #pragma unroll
        for (int ks = 0; ks < 2; ks++) {
            uint32_t aH[2][4];
            #pragma unroll
            for (int mt = 0; mt < 2; mt++) {
                int row = warp_m * 32 + mt * 16 + (lane & 15);
                int cb  = ks * 2 + (lane >> 4);
                uint32_t off = (uint32_t)(row * 64 + ((cb ^ ((row >> 1) & 3)) * 16));
                LDSM_X4(aH[mt], sb + off);
            }
            #pragma unroll
            for (int g = 0; g < 4; g++) {
                uint32_t bh[4];
                int row = warp_n * 64 + g * 16 + (lane & 15);
                int cb  = ks * 2 + (lane >> 4);
                uint32_t off = (uint32_t)(row * 64 + ((cb ^ ((row >> 1) & 3)) * 16));
                LDSM_X4(bh, sb + ASZ + off);
                #pragma unroll
                for (int mt = 0; mt < 2; mt++) {
                    #pragma unroll
                    for (int sub = 0; sub < 2; sub++) {
                        int nt = g * 2 + sub;
                        mma_fp16(acc[mt][nt], aH[mt], bh[sub], bh[sub + 2]);
                    }
                }
            }
        }
        __syncthreads();
        stage = (stage + 1 == NSTAGE) ? 0 : stage + 1;
    }

    // ---------------- epilogue ----------------
    #pragma unroll
    for (int nt = 0; nt < 8; nt++) {
        int col = block_col + warp_n * 64 + nt * 8 + (lane & 3) * 2;
        float bl0 = 0.f, bl1 = 0.f, wc0 = 0.f, wc1 = 0.f, wa0 = 0.f, wa1 = 0.f;
        if (EPI == 1) {
            bl0 = bl[col];  bl1 = bl[col + 1];
            wc0 = Wc[col];  wc1 = Wc[col + 1];
            wa0 = Wa[col];  wa1 = Wa[col + 1];
        }
        #pragma unroll
        for (int mt = 0; mt < 2; mt++) {
            int rbase = block_row + warp_m * 32 + mt * 16 + (lane >> 2);
            #pragma unroll
            for (int h = 0; h < 2; h++) {
                int row = rbase + h * 8;
                if (row >= M) continue;
                float v0 = acc[mt][nt][h * 2 + 0];
                float v1 = acc[mt][nt][h * 2 + 1];
                if (EPI == 1) {
                    float cv = cvec[row], xv = xvec[row];
                    v0 = fmaxf(v0 + bl0 + cv * wc0 + xv * wa0, 0.f);
                    v1 = fmaxf(v1 + bl1 + cv * wc1 + xv * wa1, 0.f);
                    __half2 hh;
                    hh.x = __float2half(v0);
                    hh.y = __float2half(v1);
                    *(__half2*)&g_h1h[(size_t)row * LM + col] = hh;
                } else if (EPI == 2) {
                    __half2 hh;
                    hh.x = __float2half(v0);
                    hh.y = __float2half(v1);
                    *(__half2*)&g_hp1h[(size_t)row * HH + col] = hh;
                } else {
                    float2 f2; f2.x = v0; f2.y = v1;
                    *(float2*)&g_hp3[(size_t)row * OUTC + col] = f2;
                }
            }
        }
    }
}

// ---------------- conv1 aggregation (fp16 in/out, CSR gather, warp/node) ----
// h2[d] = relu(b1 + sum coef_e * hp1[src_e] + dis[d]^2 * hp1[d])
__global__ void k_agg_h(const float* __restrict__ bias, int n) {
    int warp = (blockIdx.x * blockDim.x + threadIdx.x) >> 5;
    int lane = threadIdx.x & 31;
    if (warp >= n) return;
    const int node = warp;
    float acc[4];

    float selfc = g_dis[node] * g_dis[node];
    {
        uint2 v = *(const uint2*)&g_hp1h[(size_t)node * HH + lane * 4];
        float2 fa = __half22float2(*reinterpret_cast<__half2*>(&v.x));
        float2 fb = __half22float2(*reinterpret_cast<__half2*>(&v.y));
        acc[0] = selfc * fa.x; acc[1] = selfc * fa.y;
        acc[2] = selfc * fb.x; acc[3] = selfc * fb.y;
    }
    int beg = g_rowptr[node];
    int end = g_rowptr[node + 1];
    for (int e = beg; e < end; e++) {
        int   s  = g_csr_src[e];
        float cf = g_csr_coef[e];
        uint2 v = *(const uint2*)&g_hp1h[(size_t)s * HH + lane * 4];
        float2 fa = __half22float2(*reinterpret_cast<__half2*>(&v.x));
        float2 fb = __half22float2(*reinterpret_cast<__half2*>(&v.y));
        acc[0] = fmaf(cf, fa.x, acc[0]);
        acc[1] = fmaf(cf, fa.y, acc[1]);
        acc[2] = fmaf(cf, fb.x, acc[2]);
        acc[3] = fmaf(cf, fb.y, acc[3]);
    }
    float b0 = bias[lane * 4 + 0], b1 = bias[lane * 4 + 1];
    float b2 = bias[lane * 4 + 2], b3 = bias[lane * 4 + 3];
    __half2 o0, o1;
    o0.x = __float2half(fmaxf(acc[0] + b0, 0.f));
    o0.y = __float2half(fmaxf(acc[1] + b1, 0.f));
    o1.x = __float2half(fmaxf(acc[2] + b2, 0.f));
    o1.y = __float2half(fmaxf(acc[3] + b3, 0.f));
    uint2 ov;
    ov.x = *reinterpret_cast<uint32_t*>(&o0);
    ov.y = *reinterpret_cast<uint32_t*>(&o1);
    *(uint2*)&g_h2h[(size_t)node * HH + lane * 4] = ov;
}

// ---------------- conv3 aggregation (fp32, writes final out) ----------------
__global__ void k_agg_f(const float* __restrict__ bias, float* __restrict__ out, int n) {
    int warp = (blockIdx.x * blockDim.x + threadIdx.x) >> 5;
    int lane = threadIdx.x & 31;
    if (warp >= n) return;
    const int node = warp;
    float acc[2];

    float selfc = g_dis[node] * g_dis[node];
    {
        float2 v = *(const float2*)&g_hp3[(size_t)node * OUTC + lane * 2];
        acc[0] = selfc * v.x; acc[1] = selfc * v.y;
    }
    int beg = g_rowptr[node];
    int end = g_rowptr[node + 1];
    for (int e = beg; e < end; e++) {
        int   s  = g_csr_src[e];
        float cf = g_csr_coef[e];
        float2 v = *(const float2*)&g_hp3[(size_t)s * OUTC + lane * 2];
        acc[0] = fmaf(cf, v.x, acc[0]);
        acc[1] = fmaf(cf, v.y, acc[1]);
    }
    float2 o;
    o.x = acc[0] + bias[lane * 2 + 0];
    o.y = acc[1] + bias[lane * 2 + 1];
    *(float2*)&out[(size_t)node * OUTC + lane * 2] = o;
}

// ---------------- launch ----------------
extern "C" void kernel_launch(void* const* d_in, const int* in_sizes, int n_in,
                              void* d_out, int out_size) {
    const float* x    = (const float*)d_in[0];
    const float* xout = (const float*)d_in[1];
    const float* c    = (const float*)d_in[2];
    const void*  ei   = d_in[3];
    const float* ew   = (const float*)d_in[4];
    const float* Wa   = (const float*)d_in[5];
    const float* Wc   = (const float*)d_in[6];
    const float* Wl   = (const float*)d_in[7];
    const float* bl   = (const float*)d_in[8];
    const float* W1   = (const float*)d_in[9];
    const float* b1   = (const float*)d_in[10];
    const float* W3   = (const float*)d_in[11];
    const float* b3   = (const float*)d_in[12];
    float* out = (float*)d_out;

    const int n = in_sizes[0];
    const int e = in_sizes[3] / 2;

    const int SMEM_BIG  = 3 * 16384;   // 48 KB (GEMM1/2)
    const int SMEM_SML  = 3 * 12288;   // 36 KB (GEMM3)
    cudaFuncSetAttribute((const void*)k_gemm_mma<1, 1, 1, LM, 128, 256>,
                         cudaFuncAttributeMaxDynamicSharedMemorySize, SMEM_BIG);
    cudaFuncSetAttribute((const void*)k_gemm_mma<2, 2, 2, LM, 128, 256>,
                         cudaFuncAttributeMaxDynamicSharedMemorySize, SMEM_BIG);
    cudaFuncSetAttribute((const void*)k_gemm_mma<3, 3, 3, HH, 64, 128>,
                         cudaFuncAttributeMaxDynamicSharedMemorySize, SMEM_SML);

    // --- graph preprocessing (detect+init fused) ---
    const int nblk = (n + 1023) / 1024;
    k_prep  <<<(n + 255) / 256, 256>>>((const unsigned int*)ei, n);
    k_count <<<(e + 255) / 256, 256>>>(ei, ew, e);
    k_scanA <<<nblk, 1024>>>(n);
    k_scanB <<<nblk, 1024>>>(n, e);
    k_fill  <<<(e + 255) / 256, 256>>>(ei, ew, e);

    // --- fp16 conversion: xout, Wl^T, W1^T, W3^T ---
    {
        long long tot = (long long)n * LM;
        k_cvt_x<<<(unsigned)((tot + 511) / 512), 512>>>(xout, tot);
        k_cvt_wt<1><<<(LM * LM + 255) / 256, 256>>>(Wl, LM, LM);
        k_cvt_wt<2><<<(LM * HH + 255) / 256, 256>>>(W1, LM, HH);
        k_cvt_wt<3><<<(HH * OUTC + 255) / 256, 256>>>(W3, HH, OUTC);
    }

    // --- layer 0 (mma): h1 = relu(xout @ Wl + bl + c*Wc + x*Wa) -> fp16 ---
    {
        dim3 grid(LM / 128, (n + 127) / 128);
        k_gemm_mma<1, 1, 1, LM, 128, 256><<<grid, 256, SMEM_BIG>>>(n, c, x, Wc, Wa, bl);
    }
    // --- conv1 projection (mma): hp1 = h1 @ W1 -> fp16 ---
    {
        dim3 grid(HH / 128, (n + 127) / 128);
        k_gemm_mma<2, 2, 2, LM, 128, 256><<<grid, 256, SMEM_BIG>>>(n, nullptr, nullptr, nullptr, nullptr, nullptr);
    }
    // --- conv1 aggregation + bias + relu: h2 (fp16) ---
    k_agg_h<<<(n * 32 + 255) / 256, 256>>>(b1, n);

    // --- conv3 projection (mma): hp3 = h2 @ W3 -> fp32 ---
    {
        dim3 grid(1, (n + 127) / 128);
        k_gemm_mma<3, 3, 3, HH, 64, 128><<<grid, 128, SMEM_SML>>>(n, nullptr, nullptr, nullptr, nullptr, nullptr);
    }
    // --- conv3 aggregation + bias: out (fp32) ---
    k_agg_f<<<(n * 32 + 255) / 256, 256>>>(b3, out, n);
}

// round 14
// speedup vs baseline: 2.6625x; 1.2599x over previous
#include <cuda_runtime.h>
#include <cuda_fp16.h>
#include <cstdint>

// Problem constants (fixed shapes for this problem instance)
#define NN   50000
#define EE   800000
#define LM   1024
#define HH   128
#define OUTC 64

// ---------------- scratch (static __device__, no allocation) ----------------
__device__ __half g_h1h[(size_t)NN * LM];   // h1 fp16
__device__ __half g_wth [(size_t)LM * LM];  // Wl^T fp16  [1024,1024]
__device__ __half g_w1th[(size_t)HH * LM];  // W1^T fp16  [128,1024]
__device__ __half g_w3t [(size_t)OUTC * HH];// W3^T fp16  [64,128]
__device__ __half g_hp1h[(size_t)NN * HH];  // h1 @ W1 (fp16)
__device__ __half g_h2h [(size_t)NN * HH];  // conv1 output relu'd (fp16)
__device__ float  g_hp3[(size_t)NN * OUTC]; // h2 @ W3 (fp32)
__device__ float g_deg [NN];
__device__ float g_dis [NN];
__device__ int   g_cnt [NN];
__device__ int   g_rowptr[NN + 1];
__device__ int   g_bsum[64];
__device__ int   g_csr_src [EE];
__device__ float g_csr_coef[EE];
__device__ int   g_is64;

// ---------------- portable PTX helpers (sm_80+, compile for compute_103) ----
__device__ __forceinline__ uint32_t smem_to_u32(const void* p) {
    uint32_t a;
    asm("{ .reg .u64 t; cvta.to.shared.u64 t, %1; cvt.u32.u64 %0, t; }" : "=r"(a) : "l"(p));
    return a;
}
#define CP_ASYNC16(saddr, gaddr, sz) \
    asm volatile("cp.async.cg.shared.global [%0], [%1], 16, %2;" \
        :: "r"(saddr), "l"(gaddr), "r"(sz))
#define CP_COMMIT() asm volatile("cp.async.commit_group;" ::: "memory")
#define CP_WAIT(n)  asm volatile("cp.async.wait_group %0;" :: "n"(n) : "memory")
#define LDSM_X4(R, ADDR) \
    asm volatile("ldmatrix.sync.aligned.m8n8.x4.shared.b16 {%0,%1,%2,%3}, [%4];" \
        : "=r"((R)[0]), "=r"((R)[1]), "=r"((R)[2]), "=r"((R)[3]) : "r"(ADDR))

__device__ __forceinline__ void mma_fp16(float* d, const uint32_t* a,
                                         uint32_t b0, uint32_t b1) {
    asm volatile(
        "mma.sync.aligned.m16n8k16.row.col.f32.f16.f16.f32 "
        "{%0,%1,%2,%3}, {%4,%5,%6,%7}, {%8,%9}, {%0,%1,%2,%3};"
        : "+f"(d[0]), "+f"(d[1]), "+f"(d[2]), "+f"(d[3])
        : "r"(a[0]), "r"(a[1]), "r"(a[2]), "r"(a[3]), "r"(b0), "r"(b1));
}

// ---------------- buffer selectors (avoid host symbol lookups) ----------------
__device__ __forceinline__ const __half* sel_a(int SEL) {
    if (SEL == 2) return g_h1h;
    return g_h2h;
}
__device__ __forceinline__ const __half* sel_b(int SEL) {
    if (SEL == 1) return g_wth;
    if (SEL == 2) return g_w1th;
    return g_w3t;
}

// edge index fetch honoring detected dtype
__device__ __forceinline__ int edge_at(const void* ei, long long idx) {
    if (g_is64) return (int)((const long long*)ei)[idx];
    return ((const int*)ei)[idx];
}

// ---------------- fused dtype detection + init ----------------
__global__ void k_prep(const unsigned int* __restrict__ w, int n) {
    int i = blockIdx.x * blockDim.x + threadIdx.x;
    if (i == 0) {
        int is64 = 1;
        for (int j = 1; j < 64; j += 2)
            if (w[j] != 0u) { is64 = 0; break; }
        g_is64 = is64;
    }
    if (i < n) { g_deg[i] = 1.0f; g_cnt[i] = 0; }
}

__global__ void k_count(const void* __restrict__ ei, const float* __restrict__ ew, int e_) {
    int e = blockIdx.x * blockDim.x + threadIdx.x;
    if (e >= e_) return;
    int d = edge_at(ei, (long long)e_ + e);
    atomicAdd(&g_deg[d], ew[e]);
    atomicAdd(&g_cnt[d], 1);
}

// multi-block scan, phase A: per-block local exclusive scan + block totals
__global__ void k_scanA(int n) {
    __shared__ int wsum[32];
    int tid  = threadIdx.x;
    int warp = tid >> 5;
    int idx  = blockIdx.x * 1024 + tid;
    int v = (idx < n) ? g_cnt[idx] : 0;
    int inc = v;
    #pragma unroll
    for (int o = 1; o < 32; o <<= 1) {
        int nb = __shfl_up_sync(0xffffffffu, inc, o);
        if ((tid & 31) >= o) inc += nb;
    }
    if ((tid & 31) == 31) wsum[warp] = inc;
    __syncthreads();
    if (tid < 32) {
        int w = wsum[tid];
        #pragma unroll
        for (int o = 1; o < 32; o <<= 1) {
            int nb = __shfl_up_sync(0xffffffffu, w, o);
            if (tid >= o) w += nb;
        }
        wsum[tid] = w;
    }
    __syncthreads();
    int excl = inc - v + ((warp > 0) ? wsum[warp - 1] : 0);
    if (idx < n) {
        g_rowptr[idx] = excl;
        g_cnt[idx]    = 0;
        g_dis[idx]    = rsqrtf(g_deg[idx]);
    }
    if (tid == 0) g_bsum[blockIdx.x] = wsum[31];
}

// phase B: add block offsets
__global__ void k_scanB(int n, int e_) {
    __shared__ int s_off;
    int tid = threadIdx.x;
    if (tid < 32) {
        int acc = 0;
        for (int i = tid; i < (int)blockIdx.x; i += 32) acc += g_bsum[i];
        #pragma unroll
        for (int o = 16; o > 0; o >>= 1)
            acc += __shfl_down_sync(0xffffffffu, acc, o);
        if (tid == 0) s_off = acc;
    }
    __syncthreads();
    int idx = blockIdx.x * 1024 + tid;
    if (idx < n) g_rowptr[idx] += s_off;
    if (idx == n - 1) g_rowptr[n] = e_;
}

__global__ void k_fill(const void* __restrict__ ei, const float* __restrict__ ew, int e_) {
    int e = blockIdx.x * blockDim.x + threadIdx.x;
    if (e >= e_) return;
    int s = edge_at(ei, e);
    int d = edge_at(ei, (long long)e_ + e);
    int p = g_rowptr[d] + atomicAdd(&g_cnt[d], 1);
    g_csr_src[p]  = s;
    g_csr_coef[p] = g_dis[s] * ew[e] * g_dis[d];
}

// ---------------- fused weight transpose+convert (all three W) -------------
__global__ void k_cvt_w(const float* __restrict__ Wl, const float* __restrict__ W1,
                        const float* __restrict__ W3) {
    int idx = blockIdx.x * blockDim.x + threadIdx.x;
    if (idx < LM * LM) {
        int k = idx / LM, nn = idx % LM;
        g_wth[(size_t)nn * LM + k] = __float2half(Wl[idx]);
        return;
    }
    idx -= LM * LM;
    if (idx < LM * HH) {
        int k = idx / HH, nn = idx % HH;
        g_w1th[(size_t)nn * LM + k] = __float2half(W1[idx]);
        return;
    }
    idx -= LM * HH;
    if (idx < HH * OUTC) {
        int k = idx / OUTC, nn = idx % OUTC;
        g_w3t[(size_t)nn * HH + k] = __float2half(W3[idx]);
    }
}

// ---------------- mma.sync fp16 GEMM (generalized) ----------------
// D[M, *] = A[M,KDIM] @ B^T, fp16 x fp16 -> fp32 accum.
// Block 128xBN, BK=32, warp tile 32x64.
// AF32=1: A is fp32 in gmem; LDG float4 -> cvt -> STS, 2-stage smem A;
//         B via 3-stage cp.async. (requires THREADS==256)
// AF32=0: A+B both via 3-stage cp.async (fp16 gmem planes), strided loops
//         (correct for any THREADS).
// EPI=1: layer0 epilogue (bias+rank1+relu), fp16 -> g_h1h (stride LM)
// EPI=2: fp16 -> g_hp1h (stride HH)
// EPI=3: fp32 -> g_hp3  (stride OUTC)
template <int EPI, int AF32, int ASEL, int BSEL, int KDIM, int BN, int THREADS>
__global__ __launch_bounds__(THREADS)
void k_gemm_mma(int M, const float* __restrict__ Af32,
                const float* __restrict__ cvec, const float* __restrict__ xvec,
                const float* __restrict__ Wc,   const float* __restrict__ Wa,
                const float* __restrict__ bl) {
    constexpr int BK  = 32;
    constexpr int NIT = KDIM / BK;
    constexpr int ASZ = 8192;               // 128 rows x 32 fp16
    constexpr int BSZ = BN * BK * 2;
    constexpr int NSTAGE = 3;

    extern __shared__ char smem[];
    const uint32_t sbase0 = smem_to_u32(smem);
    // AF32 layout: [A0 8K][A1 8K][B0][B1][B2]
    // else  layout: [(A+B) stage0][stage1][stage2]
    const uint32_t bbase = AF32 ? (sbase0 + 2 * ASZ) : sbase0;
    constexpr int BSTRIDE = AF32 ? BSZ : (ASZ + BSZ);
    constexpr uint32_t BOFF = AF32 ? 0 : ASZ;

    const int tid    = threadIdx.x;
    const int lane   = tid & 31;
    const int wid    = tid >> 5;
    const int warp_m = wid & 3;
    const int warp_n = wid >> 2;

    const int block_row = blockIdx.y * 128;
    const int block_col = blockIdx.x * BN;

    const __half* __restrict__ Ah = sel_a(ASEL);
    const __half* __restrict__ Bh = sel_b(BSEL);

    // AF32 fixed-slot mapping (valid only for THREADS==256)
    const int r0  = tid >> 2,          cb0 = tid & 3;
    const int r1  = (tid + 256) >> 2,  cb1 = tid & 3;
    const uint32_t so0 = (uint32_t)(r0 * 64 + ((cb0 ^ ((r0 >> 1) & 3)) * 16));
    const uint32_t so1 = (uint32_t)(r1 * 64 + ((cb1 ^ ((r1 >> 1) & 3)) * 16));

    auto issue_B = [&](int stage, int k0) {
        uint32_t sb = bbase + stage * BSTRIDE + BOFF;
        #pragma unroll
        for (int i = tid; i < BN * 4; i += THREADS) {
            int r = i >> 2, cb = i & 3;
            uint32_t so = (uint32_t)(r * 64 + ((cb ^ ((r >> 1) & 3)) * 16));
            size_t gb = (size_t)(block_col + r) * KDIM + k0 + cb * 8;
            CP_ASYNC16(sb + so, (const char*)(Bh + gb), 16u);
        }
        CP_COMMIT();
    };
    // strided loop: correct for any THREADS (fix for the R13 NaN)
    auto issue_A_async = [&](int stage, int k0) {   // AF32==0 path
        uint32_t sb = bbase + stage * BSTRIDE;      // A at stage base
        #pragma unroll
        for (int i = tid; i < 512; i += THREADS) {
            int r = i >> 2, cb = i & 3;
            uint32_t so = (uint32_t)(r * 64 + ((cb ^ ((r >> 1) & 3)) * 16));
            long long arow = block_row + r;
            size_t ga = (size_t)arow * KDIM + k0 + cb * 8;
            uint32_t asz = (arow < M) ? 16u : 0u;
            CP_ASYNC16(sb + so, (const char*)(Ah + ga), asz);
        }
    };

    // fp32 A register staging (AF32==1, THREADS==256)
    float4 arg[4];
    auto ldg_A = [&](int k0) {
        long long arow0 = block_row + r0;
        long long arow1 = block_row + r1;
        if (arow0 < M) {
            const float* p = Af32 + (size_t)arow0 * KDIM + k0 + cb0 * 8;
            arg[0] = *(const float4*)p;
            arg[1] = *(const float4*)(p + 4);
        } else {
            arg[0] = arg[1] = make_float4(0.f, 0.f, 0.f, 0.f);
        }
        if (arow1 < M) {
            const float* p = Af32 + (size_t)arow1 * KDIM + k0 + cb1 * 8;
            arg[2] = *(const float4*)p;
            arg[3] = *(const float4*)(p + 4);
        } else {
            arg[2] = arg[3] = make_float4(0.f, 0.f, 0.f, 0.f);
        }
    };
    auto sts_A = [&](int buf) {
        uint32_t off = buf * ASZ;
        uint4 v;
        __half2 h;
        h = __floats2half2_rn(arg[0].x, arg[0].y); v.x = *(uint32_t*)&h;
        h = __floats2half2_rn(arg[0].z, arg[0].w); v.y = *(uint32_t*)&h;
        h = __floats2half2_rn(arg[1].x, arg[1].y); v.z = *(uint32_t*)&h;
        h = __floats2half2_rn(arg[1].z, arg[1].w); v.w = *(uint32_t*)&h;
        *(uint4*)(smem + off + so0) = v;
        h = __floats2half2_rn(arg[2].x, arg[2].y); v.x = *(uint32_t*)&h;
        h = __floats2half2_rn(arg[2].z, arg[2].w); v.y = *(uint32_t*)&h;
        h = __floats2half2_rn(arg[3].x, arg[3].y); v.z = *(uint32_t*)&h;
        h = __floats2half2_rn(arg[3].z, arg[3].w); v.w = *(uint32_t*)&h;
        *(uint4*)(smem + off + so1) = v;
    };

    float acc[2][8][4];
    #pragma unroll
    for (int i = 0; i < 2; i++)
        #pragma unroll
        for (int j = 0; j < 8; j++)
            #pragma unroll
            for (int q = 0; q < 4; q++) acc[i][j][q] = 0.0f;

    // ---- prologue ----
    if (AF32) {
        ldg_A(0);
        issue_B(0, 0);
        issue_B(1, BK);
        sts_A(0);
        CP_WAIT(1);          // B(0) ready
        __syncthreads();
    } else {
        issue_A_async(0, 0); issue_B(0, 0);
        issue_A_async(1, BK); issue_B(1, BK);
    }

    int stage = 0;
    for (int it = 0; it < NIT; it++) {
        if (AF32) {
            if (it + 1 < NIT) ldg_A((it + 1) * BK);
            if (it + 2 < NIT) issue_B((it + 2) % NSTAGE, (it + 2) * BK);
        } else {
            if (it + 2 < NIT) {
                issue_A_async((it + 2) % NSTAGE, (it + 2) * BK);
                issue_B((it + 2) % NSTAGE, (it + 2) * BK);
                CP_WAIT(2);
            } else {
                CP_WAIT(0);
            }
            __syncthreads();
        }

        const uint32_t abuf = AF32 ? (sbase0 + (it & 1) * ASZ)
                                   : (bbase + stage * BSTRIDE);
        const uint32_t bbuf = bbase + stage * BSTRIDE + BOFF;
        #pragma unroll
        for (int ks = 0; ks < 2; ks++) {
            uint32_t aH[2][4];
            #pragma unroll
            for (int mt = 0; mt < 2; mt++) {
                int row = warp_m * 32 + mt * 16 + (lane & 15);
                int cb  = ks * 2 + (lane >> 4);
                uint32_t off = (uint32_t)(row * 64 + ((cb ^ ((row >> 1) & 3)) * 16));
                LDSM_X4(aH[mt], abuf + off);
            }
            #pragma unroll
            for (int g = 0; g < 4; g++) {
                uint32_t bh[4];
                int row = warp_n * 64 + g * 16 + (lane & 15);
                int cb  = ks * 2 + (lane >> 4);
                uint32_t off = (uint32_t)(row * 64 + ((cb ^ ((row >> 1) & 3)) * 16));
                LDSM_X4(bh, bbuf + off);
                #pragma unroll
                for (int mt = 0; mt < 2; mt++) {
                    #pragma unroll
                    for (int sub = 0; sub < 2; sub++) {
                        int nt = g * 2 + sub;
                        mma_fp16(acc[mt][nt], aH[mt], bh[sub], bh[sub + 2]);
                    }
                }
            }
        }
        __syncthreads();
        if (AF32) {
            if (it + 1 < NIT) sts_A((it + 1) & 1);
            if (it + 2 < NIT) { CP_WAIT(1); }
            else if (it + 1 < NIT) { CP_WAIT(0); }
            __syncthreads();
        }
        stage = (stage + 1 == NSTAGE) ? 0 : stage + 1;
    }

    // ---------------- epilogue ----------------
    #pragma unroll
    for (int nt = 0; nt < 8; nt++) {
        int col = block_col + warp_n * 64 + nt * 8 + (lane & 3) * 2;
        float bl0 = 0.f, bl1 = 0.f, wc0 = 0.f, wc1 = 0.f, wa0 = 0.f, wa1 = 0.f;
        if (EPI == 1) {
            bl0 = bl[col];  bl1 = bl[col + 1];
            wc0 = Wc[col];  wc1 = Wc[col + 1];
            wa0 = Wa[col];  wa1 = Wa[col + 1];
        }
        #pragma unroll
        for (int mt = 0; mt < 2; mt++) {
            int rbase = block_row + warp_m * 32 + mt * 16 + (lane >> 2);
            #pragma unroll
            for (int h = 0; h < 2; h++) {
                int row = rbase + h * 8;
                if (row >= M) continue;
                float v0 = acc[mt][nt][h * 2 + 0];
                float v1 = acc[mt][nt][h * 2 + 1];
                if (EPI == 1) {
                    float cv = cvec[row], xv = xvec[row];
                    v0 = fmaxf(v0 + bl0 + cv * wc0 + xv * wa0, 0.f);
                    v1 = fmaxf(v1 + bl1 + cv * wc1 + xv * wa1, 0.f);
                    __half2 hh;
                    hh.x = __float2half(v0);
                    hh.y = __float2half(v1);
                    *(__half2*)&g_h1h[(size_t)row * LM + col] = hh;
                } else if (EPI == 2) {
                    __half2 hh;
                    hh.x = __float2half(v0);
                    hh.y = __float2half(v1);
                    *(__half2*)&g_hp1h[(size_t)row * HH + col] = hh;
                } else {
                    float2 f2; f2.x = v0; f2.y = v1;
                    *(float2*)&g_hp3[(size_t)row * OUTC + col] = f2;
                }
            }
        }
    }
}

// ---------------- conv1 aggregation (fp16 in/out, CSR gather, warp/node) ----
__global__ void k_agg_h(const float* __restrict__ bias, int n) {
    int warp = (blockIdx.x * blockDim.x + threadIdx.x) >> 5;
    int lane = threadIdx.x & 31;
    if (warp >= n) return;
    const int node = warp;
    float acc[4];

    float selfc = g_dis[node] * g_dis[node];
    {
        uint2 v = *(const uint2*)&g_hp1h[(size_t)node * HH + lane * 4];
        float2 fa = __half22float2(*reinterpret_cast<__half2*>(&v.x));
        float2 fb = __half22float2(*reinterpret_cast<__half2*>(&v.y));
        acc[0] = selfc * fa.x; acc[1] = selfc * fa.y;
        acc[2] = selfc * fb.x; acc[3] = selfc * fb.y;
    }
    int beg = g_rowptr[node];
    int end = g_rowptr[node + 1];
    for (int e = beg; e < end; e++) {
        int   s  = g_csr_src[e];
        float cf = g_csr_coef[e];
        uint2 v = *(const uint2*)&g_hp1h[(size_t)s * HH + lane * 4];
        float2 fa = __half22float2(*reinterpret_cast<__half2*>(&v.x));
        float2 fb = __half22float2(*reinterpret_cast<__half2*>(&v.y));
        acc[0] = fmaf(cf, fa.x, acc[0]);
        acc[1] = fmaf(cf, fa.y, acc[1]);
        acc[2] = fmaf(cf, fb.x, acc[2]);
        acc[3] = fmaf(cf, fb.y, acc[3]);
    }
    float b0 = bias[lane * 4 + 0], b1 = bias[lane * 4 + 1];
    float b2 = bias[lane * 4 + 2], b3 = bias[lane * 4 + 3];
    __half2 o0, o1;
    o0.x = __float2half(fmaxf(acc[0] + b0, 0.f));
    o0.y = __float2half(fmaxf(acc[1] + b1, 0.f));
    o1.x = __float2half(fmaxf(acc[2] + b2, 0.f));
    o1.y = __float2half(fmaxf(acc[3] + b3, 0.f));
    uint2 ov;
    ov.x = *reinterpret_cast<uint32_t*>(&o0);
    ov.y = *reinterpret_cast<uint32_t*>(&o1);
    *(uint2*)&g_h2h[(size_t)node * HH + lane * 4] = ov;
}

// ---------------- conv3 aggregation (fp32, writes final out) ----------------
__global__ void k_agg_f(const float* __restrict__ bias, float* __restrict__ out, int n) {
    int warp = (blockIdx.x * blockDim.x + threadIdx.x) >> 5;
    int lane = threadIdx.x & 31;
    if (warp >= n) return;
    const int node = warp;
    float acc[2];

    float selfc = g_dis[node] * g_dis[node];
    {
        float2 v = *(const float2*)&g_hp3[(size_t)node * OUTC + lane * 2];
        acc[0] = selfc * v.x; acc[1] = selfc * v.y;
    }
    int beg = g_rowptr[node];
    int end = g_rowptr[node + 1];
    for (int e = beg; e < end; e++) {
        int   s  = g_csr_src[e];
        float cf = g_csr_coef[e];
        float2 v = *(const float2*)&g_hp3[(size_t)s * OUTC + lane * 2];
        acc[0] = fmaf(cf, v.x, acc[0]);
        acc[1] = fmaf(cf, v.y, acc[1]);
    }
    float2 o;
    o.x = acc[0] + bias[lane * 2 + 0];
    o.y = acc[1] + bias[lane * 2 + 1];
    *(float2*)&out[(size_t)node * OUTC + lane * 2] = o;
}

// ---------------- launch ----------------
extern "C" void kernel_launch(void* const* d_in, const int* in_sizes, int n_in,
                              void* d_out, int out_size) {
    const float* x    = (const float*)d_in[0];
    const float* xout = (const float*)d_in[1];
    const float* c    = (const float*)d_in[2];
    const void*  ei   = d_in[3];
    const float* ew   = (const float*)d_in[4];
    const float* Wa   = (const float*)d_in[5];
    const float* Wc   = (const float*)d_in[6];
    const float* Wl   = (const float*)d_in[7];
    const float* bl   = (const float*)d_in[8];
    const float* W1   = (const float*)d_in[9];
    const float* b1   = (const float*)d_in[10];
    const float* W3   = (const float*)d_in[11];
    const float* b3   = (const float*)d_in[12];
    float* out = (float*)d_out;

    const int n = in_sizes[0];
    const int e = in_sizes[3] / 2;

    const int SMEM_G1  = 2 * 8192 + 3 * 8192;   // 40 KB (A 2-stage + B 3-stage)
    const int SMEM_G2  = 3 * 16384;             // 48 KB
    const int SMEM_G3  = 3 * 12288;             // 36 KB
    cudaFuncSetAttribute((const void*)k_gemm_mma<1, 1, 0, 1, LM, 128, 256>,
                         cudaFuncAttributeMaxDynamicSharedMemorySize, SMEM_G1);
    cudaFuncSetAttribute((const void*)k_gemm_mma<2, 0, 2, 2, LM, 128, 256>,
                         cudaFuncAttributeMaxDynamicSharedMemorySize, SMEM_G2);
    cudaFuncSetAttribute((const void*)k_gemm_mma<3, 0, 3, 3, HH, 64, 128>,
                         cudaFuncAttributeMaxDynamicSharedMemorySize, SMEM_G3);

    // --- graph preprocessing (detect+init fused) ---
    const int nblk = (n + 1023) / 1024;
    k_prep  <<<(n + 255) / 256, 256>>>((const unsigned int*)ei, n);
    k_count <<<(e + 255) / 256, 256>>>(ei, ew, e);
    k_scanA <<<nblk, 1024>>>(n);
    k_scanB <<<nblk, 1024>>>(n, e);
    k_fill  <<<(e + 255) / 256, 256>>>(ei, ew, e);

    // --- weight transpose+convert (single fused launch) ---
    {
        const int tot = LM * LM + LM * HH + HH * OUTC;
        k_cvt_w<<<(tot + 255) / 256, 256>>>(Wl, W1, W3);
    }

    // --- layer 0 (mma, fused fp32->fp16 A-load):
    //     h1 = relu(xout @ Wl + bl + c*Wc + x*Wa) -> fp16 ---
    {
        dim3 grid(LM / 128, (n + 127) / 128);
        k_gemm_mma<1, 1, 0, 1, LM, 128, 256><<<grid, 256, SMEM_G1>>>(
            n, xout, c, x, Wc, Wa, bl);
    }
    // --- conv1 projection (mma): hp1 = h1 @ W1 -> fp16 ---
    {
        dim3 grid(HH / 128, (n + 127) / 128);
        k_gemm_mma<2, 0, 2, 2, LM, 128, 256><<<grid, 256, SMEM_G2>>>(
            n, nullptr, nullptr, nullptr, nullptr, nullptr, nullptr);
    }
    // --- conv1 aggregation + bias + relu: h2 (fp16) ---
    k_agg_h<<<(n * 32 + 255) / 256, 256>>>(b1, n);

    // --- conv3 projection (mma): hp3 = h2 @ W3 -> fp32 ---
    {
        dim3 grid(1, (n + 127) / 128);
        k_gemm_mma<3, 0, 3, 3, HH, 64, 128><<<grid, 128, SMEM_G3>>>(
            n, nullptr, nullptr, nullptr, nullptr, nullptr, nullptr);
    }
    // --- conv3 aggregation + bias: out (fp32) ---
    k_agg_f<<<(n * 32 + 255) / 256, 256>>>(b3, out, n);
}